// round 2
// baseline (speedup 1.0000x reference)
#include <cuda_runtime.h>

#define NB 128
#define NC 500
#define HWD 16
#define HW 256
#define NPIX (NB*HW)          // 32768
#define C1 300
#define C2 100

// ---------------- device scratch (no allocations allowed) ----------------
__device__ float g_l1[NC];
__device__ float g_wl1[NC*16*C1];        // [c][kh*4+kw][co]
__device__ float g_xt[(size_t)NPIX*NC];  // [pix][c]
__device__ int   g_seln[NPIX];
__device__ short g_selc[NPIX*30];
__device__ float g_self[NPIX*30];
__device__ float g_y1[(size_t)NB*34*34*C1];   // NHWC
__device__ float g_w2m[9*C1*C2];              // [dy][dx][c1][c2]
__device__ float g_y2[(size_t)NB*36*36*C2];   // NHWC
__device__ float g_w3m[9*C2*3];               // [dy][dx][c1][c3]

// ---------------- l1[c] = sum_d |phi[d][c]| + 1e-12 ----------------
__global__ void k_l1(const float* __restrict__ phi) {
    int c = threadIdx.x;
    if (c < NC) {
        float s = 0.f;
        for (int d = 0; d < 192; d++) s += fabsf(phi[d*NC + c]);
        g_l1[c] = s + 1e-12f;
    }
}

// ---------------- wl1[c][kk][co] = l1[c]*w1[c][co][kk] ----------------
__global__ void k_wl1(const float* __restrict__ w1) {
    int e = blockIdx.x*256 + threadIdx.x;
    if (e >= NC*16*C1) return;
    int co = e % C1;
    int r  = e / C1;
    int kk = r % 16;
    int c  = r / 16;
    g_wl1[e] = g_l1[c] * w1[(c*C1 + co)*16 + kk];
}

// ---------------- w2m[dy][dx][c1][c2] = w2[c1][c2][dy][dx] ----------------
__global__ void k_w2m(const float* __restrict__ w2) {
    int e = blockIdx.x*256 + threadIdx.x;
    if (e >= 9*C1*C2) return;
    int c2 = e % C2;
    int t  = e / C2;
    int c1 = t % C1;
    int dd = t / C1;
    int dy = dd / 3, dx = dd % 3;
    g_w2m[e] = w2[((c1*C2 + c2)*3 + dy)*3 + dx];
}

// ---------------- w3m[dy][dx][c1][c3] = w3[c1][c3][dy][dx] ----------------
__global__ void k_w3m(const float* __restrict__ w3) {
    int e = blockIdx.x*256 + threadIdx.x;
    if (e >= 9*C2*3) return;
    int c3 = e % 3;
    int t  = e / 3;
    int c1 = t % C2;
    int dd = t / C2;
    int dy = dd / 3, dx = dd % 3;
    g_w3m[e] = w3[((c1*3 + c3)*3 + dy)*3 + dx];
}

// ---------------- transpose x [B][C][HW] -> xt [B][HW][C] ----------------
__global__ void k_transpose(const float* __restrict__ x) {
    __shared__ float tile[32][33];
    int b  = blockIdx.z;
    int c0 = blockIdx.x * 32;
    int h0 = blockIdx.y * 32;
    int tx = threadIdx.x, ty = threadIdx.y;
    int c = c0 + ty, hw = h0 + tx;
    if (c < NC) tile[ty][tx] = x[((size_t)b*NC + c)*HW + hw];
    __syncthreads();
    c = c0 + tx; hw = h0 + ty;
    if (c < NC) g_xt[((size_t)b*HW + hw)*NC + c] = tile[tx][ty];
}

// ---------------- top-30 + saturation -> sparse (channel, coef) ----------------
__global__ void k_topk(const float* __restrict__ jump_ptr) {
    int gwarp = (blockIdx.x * blockDim.x + threadIdx.x) >> 5;
    int lane  = threadIdx.x & 31;
    const float* xr = g_xt + (size_t)gwarp * NC;

    float v[16];
    #pragma unroll
    for (int t = 0; t < 16; t++) {
        int c = lane + t*32;
        v[t] = (c < NC) ? xr[c] : 0.f;
    }
    float jump = *jump_ptr;
    unsigned selmask = 0;
    int n = 0;

    for (int it = 0; it < 30; it++) {
        float ba = -1.f; int bi = 0x7fffffff;
        #pragma unroll
        for (int t = 0; t < 16; t++) {
            int c = lane + t*32;
            if (c < NC && !((selmask >> t) & 1u)) {
                float a = fabsf(v[t]);
                if (a > ba || (a == ba && c < bi)) { ba = a; bi = c; }
            }
        }
        #pragma unroll
        for (int off = 16; off; off >>= 1) {
            float oa = __shfl_xor_sync(0xffffffffu, ba, off);
            int   oi = __shfl_xor_sync(0xffffffffu, bi, off);
            if (oa > ba || (oa == ba && oi < bi)) { ba = oa; bi = oi; }
        }
        // bi uniform across warp now
        if (lane == (bi & 31)) selmask |= 1u << (bi >> 5);
        float xv = xr[bi];
        float l1c = g_l1[bi];
        float r = xv / l1c;
        float rm = r - jump, rp = r + jump;
        float coef = 0.5f * ((float)((rm > 0.f) - (rm < 0.f)) +
                             (float)((rp > 0.f) - (rp < 0.f)));
        if (coef != 0.f) {
            if (lane == 0) {
                g_selc[gwarp*30 + n] = (short)bi;
                g_self[gwarp*30 + n] = coef;
            }
            n++;
        }
    }
    if (lane == 0) g_seln[gwarp] = n;
}

// ---------------- conv1 (sparse, output-centric), ReLU, -> y1 NHWC ----------------
__global__ __launch_bounds__(320) void k_conv1(const float* __restrict__ b1) {
    __shared__ int   s_cnt;
    __shared__ int   s_pix[4], s_kk[4], s_n[4];
    __shared__ short s_ch[4][32];
    __shared__ float s_cf[4][32];

    int b   = blockIdx.y;
    int oy  = blockIdx.x / 34;
    int ox  = blockIdx.x % 34;
    int tid = threadIdx.x;

    if (tid == 0) {
        int cnt = 0;
        int p = oy & 1, q = ox & 1;
        for (int kh = p; kh < 4; kh += 2) {
            int iy2 = oy - kh; if (iy2 < 0) continue;
            int iy = iy2 >> 1; if (iy >= HWD) continue;
            for (int kw = q; kw < 4; kw += 2) {
                int ix2 = ox - kw; if (ix2 < 0) continue;
                int ix = ix2 >> 1; if (ix >= HWD) continue;
                int pix = (b*HWD + iy)*HWD + ix;
                s_pix[cnt] = pix;
                s_kk[cnt]  = kh*4 + kw;
                s_n[cnt]   = g_seln[pix];
                cnt++;
            }
        }
        s_cnt = cnt;
    }
    __syncthreads();
    int cnt = s_cnt;
    if (tid < 128) {
        int s = tid >> 5, t = tid & 31;
        if (s < cnt && t < s_n[s]) {
            s_ch[s][t] = g_selc[s_pix[s]*30 + t];
            s_cf[s][t] = g_self[s_pix[s]*30 + t];
        }
    }
    __syncthreads();

    int co = tid;
    if (co < C1) {
        float acc = 0.f;
        for (int s = 0; s < cnt; s++) {
            const float* wbase = g_wl1 + s_kk[s]*C1 + co;
            int ns = s_n[s];
            #pragma unroll 4
            for (int t = 0; t < ns; t++) {
                int c = (int)s_ch[s][t];
                acc += s_cf[s][t] * wbase[c*(16*C1)];
            }
        }
        float y = acc + b1[co];
        g_y1[((size_t)(b*1156 + oy*34 + ox))*C1 + co] = fmaxf(y, 0.f);
    }
}

// ---------------- conv2 (dense 300->100 3x3 transpose), ReLU -> y2 NHWC ----------------
#define CH2 30
__global__ __launch_bounds__(256) void k_conv2(const float* __restrict__ b2) {
    __shared__ __align__(16) float sw[CH2*3*C2];   // [c1l][dx][c2]
    __shared__ float sy[38*(CH2+1)];               // [ix+2][c1l], zero-padded rows

    int oy  = blockIdx.x;
    int b   = blockIdx.y;
    int tid = threadIdx.x;
    int cg  = tid % 25;       // c2 group
    int og  = tid / 25;       // ox group (active og<9)
    bool active = (tid < 225);
    int c2b = cg*4, ox0 = og*4;

    float acc[4][4];
    #pragma unroll
    for (int i = 0; i < 4; i++)
        #pragma unroll
        for (int j = 0; j < 4; j++) acc[i][j] = 0.f;

    for (int dy = 0; dy < 3; dy++) {
        int iy = oy - dy;
        if (iy < 0 || iy >= 34) continue;
        for (int c0 = 0; c0 < C1; c0 += CH2) {
            __syncthreads();
            // zero pad rows (ix+2 in {0,1,36,37})
            for (int i = tid; i < 4*(CH2+1); i += 256) {
                int r = i / (CH2+1), cl = i % (CH2+1);
                int row = (r < 2) ? r : r + 34;
                sy[row*(CH2+1) + cl] = 0.f;
            }
            for (int i = tid; i < 34*CH2; i += 256) {
                int ix = i / CH2, cl = i % CH2;
                sy[(ix+2)*(CH2+1) + cl] =
                    g_y1[((size_t)(b*1156 + iy*34 + ix))*C1 + c0 + cl];
            }
            for (int i = tid; i < CH2*3*C2; i += 256) {
                int c2 = i % C2;
                int t  = i / C2;
                int dx = t % 3;
                int c1l = t / 3;
                sw[i] = g_w2m[((dy*3 + dx)*C1 + c0 + c1l)*C2 + c2];
            }
            __syncthreads();
            if (active) {
                for (int c1l = 0; c1l < CH2; c1l++) {
                    #pragma unroll
                    for (int dx = 0; dx < 3; dx++) {
                        float4 wv = *(const float4*)(sw + (c1l*3 + dx)*C2 + c2b);
                        float y0 = sy[(ox0+2-dx)*(CH2+1) + c1l];
                        float y1v = sy[(ox0+3-dx)*(CH2+1) + c1l];
                        float y2v = sy[(ox0+4-dx)*(CH2+1) + c1l];
                        float y3v = sy[(ox0+5-dx)*(CH2+1) + c1l];
                        acc[0][0] = fmaf(y0,  wv.x, acc[0][0]);
                        acc[1][0] = fmaf(y0,  wv.y, acc[1][0]);
                        acc[2][0] = fmaf(y0,  wv.z, acc[2][0]);
                        acc[3][0] = fmaf(y0,  wv.w, acc[3][0]);
                        acc[0][1] = fmaf(y1v, wv.x, acc[0][1]);
                        acc[1][1] = fmaf(y1v, wv.y, acc[1][1]);
                        acc[2][1] = fmaf(y1v, wv.z, acc[2][1]);
                        acc[3][1] = fmaf(y1v, wv.w, acc[3][1]);
                        acc[0][2] = fmaf(y2v, wv.x, acc[0][2]);
                        acc[1][2] = fmaf(y2v, wv.y, acc[1][2]);
                        acc[2][2] = fmaf(y2v, wv.z, acc[2][2]);
                        acc[3][2] = fmaf(y2v, wv.w, acc[3][2]);
                        acc[0][3] = fmaf(y3v, wv.x, acc[0][3]);
                        acc[1][3] = fmaf(y3v, wv.y, acc[1][3]);
                        acc[2][3] = fmaf(y3v, wv.z, acc[2][3]);
                        acc[3][3] = fmaf(y3v, wv.w, acc[3][3]);
                    }
                }
            }
        }
    }
    if (active) {
        float bb[4];
        #pragma unroll
        for (int i = 0; i < 4; i++) bb[i] = b2[c2b + i];
        #pragma unroll
        for (int j = 0; j < 4; j++)
            #pragma unroll
            for (int i = 0; i < 4; i++)
                g_y2[((size_t)(b*36 + oy)*36 + (ox0+j))*C2 + c2b + i] =
                    fmaxf(acc[i][j] + bb[i], 0.f);
    }
}

// ---------------- conv3 (100->3 3x3 transpose) + ReLU + center crop ----------------
__global__ __launch_bounds__(96) void k_conv3(const float* __restrict__ b3,
                                              float* __restrict__ out) {
    __shared__ float s_y2[3*35*50];
    __shared__ float s_w3[9*C2*3];

    int u   = blockIdx.x;   // output row in crop
    int b   = blockIdx.y;
    int tid = threadIdx.x;  // 96
    int v   = tid % 32;
    int c3  = tid / 32;

    for (int i = tid; i < 9*C2*3; i += 96) s_w3[i] = g_w3m[i];

    float acc = 0.f;
    for (int c0 = 0; c0 < C2; c0 += 50) {
        __syncthreads();
        for (int i = tid; i < 3*35*50; i += 96) {
            int cl = i % 50;
            int t  = i / 50;
            int ix = t % 35;
            int r  = t / 35;
            s_y2[i] = g_y2[((size_t)(b*36 + (u+1+r))*36 + (ix+1))*C2 + c0 + cl];
        }
        __syncthreads();
        for (int dy = 0; dy < 3; dy++) {
            int r = 2 - dy;   // row u+3-dy stored at r
            #pragma unroll
            for (int dx = 0; dx < 3; dx++) {
                int col = v + 2 - dx;   // ix = v+3-dx stored at ix-1
                const float* yrow = s_y2 + (r*35 + col)*50;
                const float* wrow = s_w3 + ((dy*3 + dx)*C2 + c0)*3 + c3;
                #pragma unroll 10
                for (int c = 0; c < 50; c++) acc += yrow[c] * wrow[c*3];
            }
        }
    }
    out[((b*3 + c3)*32 + u)*32 + v] = fmaxf(acc + b3[c3], 0.f);
}

// ---------------- launch ----------------
extern "C" void kernel_launch(void* const* d_in, const int* in_sizes, int n_in,
                              void* d_out, int out_size) {
    const float* x    = (const float*)d_in[0];
    const float* phi  = (const float*)d_in[1];
    const float* jump = (const float*)d_in[2];
    const float* w1   = (const float*)d_in[3];
    const float* b1   = (const float*)d_in[4];
    const float* w2   = (const float*)d_in[5];
    const float* b2   = (const float*)d_in[6];
    const float* w3   = (const float*)d_in[7];
    const float* b3   = (const float*)d_in[8];
    float* out = (float*)d_out;

    k_l1<<<1, 512>>>(phi);
    k_wl1<<<(NC*16*C1 + 255)/256, 256>>>(w1);
    k_w2m<<<(9*C1*C2 + 255)/256, 256>>>(w2);
    k_w3m<<<(9*C2*3 + 255)/256, 256>>>(w3);
    k_transpose<<<dim3(16, 8, NB), dim3(32, 32)>>>(x);
    k_topk<<<4096, 256>>>(jump);
    k_conv1<<<dim3(34*34, NB), 320>>>(b1);
    k_conv2<<<dim3(36, NB), 256>>>(b2);
    k_conv3<<<dim3(32, NB), 96>>>(b3, out);
}

// round 3
// speedup vs baseline: 1.2042x; 1.2042x over previous
#include <cuda_runtime.h>
#include <cuda_fp16.h>

#define NB 128
#define NC 500
#define HWD 16
#define HW 256
#define NPIX (NB*HW)          // 32768
#define C1 300
#define C2 100

// ---------------- device scratch (no allocations allowed) ----------------
__device__ float  g_l1[NC];
__device__ __half g_wl1h[NC*16*C1];       // [c][kh*4+kw][co]  (fp16, pre-scaled by l1)
__device__ float  g_xt[(size_t)NPIX*NC];  // [pix][c]
__device__ int    g_seln[NPIX];
__device__ short  g_selc[NPIX*30];
__device__ float  g_self[NPIX*30];
__device__ float  g_y1[(size_t)NB*34*34*C1];   // NHWC
__device__ float  g_w2m[9*C1*C2];              // [dy][dx][c1][c2]
__device__ float  g_y2[(size_t)NB*36*36*C2];   // NHWC
__device__ float  g_w3m[9*C2*3];               // [dy][dx][c1][c3]

// ---------------- f32x2 packed-FMA helpers (sm_10x) ----------------
__device__ __forceinline__ unsigned long long pk2(float v) {
    unsigned long long r;
    asm("mov.b64 %0,{%1,%1};" : "=l"(r) : "f"(v));
    return r;
}
__device__ __forceinline__ void fma2(unsigned long long& d,
                                     unsigned long long a, unsigned long long b) {
    asm("fma.rn.f32x2 %0,%1,%2,%0;" : "+l"(d) : "l"(a), "l"(b));
}
__device__ __forceinline__ float2 upk(unsigned long long v) {
    float2 r;
    asm("mov.b64 {%0,%1},%2;" : "=f"(r.x), "=f"(r.y) : "l"(v));
    return r;
}

// ---------------- l1[c] = sum_d |phi[d][c]| + 1e-12 ----------------
__global__ void k_l1(const float* __restrict__ phi) {
    int c = threadIdx.x;
    if (c < NC) {
        float s = 0.f;
        for (int d = 0; d < 192; d++) s += fabsf(phi[d*NC + c]);
        g_l1[c] = s + 1e-12f;
    }
}

// ---------------- wl1h[c][kk][co] = fp16( l1[c]*w1[c][co][kk] ) ----------------
__global__ void k_wl1(const float* __restrict__ w1) {
    int e = blockIdx.x*256 + threadIdx.x;
    if (e >= NC*16*C1) return;
    int co = e % C1;
    int r  = e / C1;
    int kk = r % 16;
    int c  = r / 16;
    g_wl1h[e] = __float2half(g_l1[c] * w1[(c*C1 + co)*16 + kk]);
}

// ---------------- w2m[dy][dx][c1][c2] = w2[c1][c2][dy][dx] ----------------
__global__ void k_w2m(const float* __restrict__ w2) {
    int e = blockIdx.x*256 + threadIdx.x;
    if (e >= 9*C1*C2) return;
    int c2 = e % C2;
    int t  = e / C2;
    int c1 = t % C1;
    int dd = t / C1;
    int dy = dd / 3, dx = dd % 3;
    g_w2m[e] = w2[((c1*C2 + c2)*3 + dy)*3 + dx];
}

// ---------------- w3m[dy][dx][c1][c3] = w3[c1][c3][dy][dx] ----------------
__global__ void k_w3m(const float* __restrict__ w3) {
    int e = blockIdx.x*256 + threadIdx.x;
    if (e >= 9*C2*3) return;
    int c3 = e % 3;
    int t  = e / 3;
    int c1 = t % C2;
    int dd = t / C2;
    int dy = dd / 3, dx = dd % 3;
    g_w3m[e] = w3[((c1*3 + c3)*3 + dy)*3 + dx];
}

// ---------------- transpose x [B][C][HW] -> xt [B][HW][C] ----------------
__global__ void k_transpose(const float* __restrict__ x) {
    __shared__ float tile[32][33];
    int b  = blockIdx.z;
    int c0 = blockIdx.x * 32;
    int h0 = blockIdx.y * 32;
    int tx = threadIdx.x, ty = threadIdx.y;
    int c = c0 + ty, hw = h0 + tx;
    if (c < NC) tile[ty][tx] = x[((size_t)b*NC + c)*HW + hw];
    __syncthreads();
    c = c0 + tx; hw = h0 + ty;
    if (c < NC) g_xt[((size_t)b*HW + hw)*NC + c] = tile[tx][ty];
}

// ---------------- top-30 + saturation -> sparse (channel, coef) ----------------
__global__ void k_topk(const float* __restrict__ jump_ptr) {
    int gwarp = (blockIdx.x * blockDim.x + threadIdx.x) >> 5;
    int lane  = threadIdx.x & 31;
    const float* xr = g_xt + (size_t)gwarp * NC;

    float v[16];
    #pragma unroll
    for (int t = 0; t < 16; t++) {
        int c = lane + t*32;
        v[t] = (c < NC) ? xr[c] : 0.f;
    }
    float jump = *jump_ptr;
    unsigned selmask = 0;
    int n = 0;

    for (int it = 0; it < 30; it++) {
        float ba = -1.f; int bi = 0x7fffffff;
        #pragma unroll
        for (int t = 0; t < 16; t++) {
            int c = lane + t*32;
            if (c < NC && !((selmask >> t) & 1u)) {
                float a = fabsf(v[t]);
                if (a > ba || (a == ba && c < bi)) { ba = a; bi = c; }
            }
        }
        #pragma unroll
        for (int off = 16; off; off >>= 1) {
            float oa = __shfl_xor_sync(0xffffffffu, ba, off);
            int   oi = __shfl_xor_sync(0xffffffffu, bi, off);
            if (oa > ba || (oa == ba && oi < bi)) { ba = oa; bi = oi; }
        }
        if (lane == (bi & 31)) selmask |= 1u << (bi >> 5);
        float xv = xr[bi];
        float l1c = g_l1[bi];
        float r = xv / l1c;
        float rm = r - jump, rp = r + jump;
        float coef = 0.5f * ((float)((rm > 0.f) - (rm < 0.f)) +
                             (float)((rp > 0.f) - (rp < 0.f)));
        if (coef != 0.f) {
            if (lane == 0) {
                g_selc[gwarp*30 + n] = (short)bi;
                g_self[gwarp*30 + n] = coef;
            }
            n++;
        }
    }
    if (lane == 0) g_seln[gwarp] = n;
}

// ---------------- conv1 (sparse, fp16 table, half2 per thread) ----------------
__global__ __launch_bounds__(160) void k_conv1(const float* __restrict__ b1) {
    __shared__ int   s_cnt;
    __shared__ int   s_pix[4], s_kk[4], s_n[4];
    __shared__ short s_ch[4][32];
    __shared__ float s_cf[4][32];

    int b   = blockIdx.y;
    int oy  = blockIdx.x / 34;
    int ox  = blockIdx.x % 34;
    int tid = threadIdx.x;

    if (tid == 0) {
        int cnt = 0;
        int p = oy & 1, q = ox & 1;
        for (int kh = p; kh < 4; kh += 2) {
            int iy2 = oy - kh; if (iy2 < 0) continue;
            int iy = iy2 >> 1; if (iy >= HWD) continue;
            for (int kw = q; kw < 4; kw += 2) {
                int ix2 = ox - kw; if (ix2 < 0) continue;
                int ix = ix2 >> 1; if (ix >= HWD) continue;
                int pix = (b*HWD + iy)*HWD + ix;
                s_pix[cnt] = pix;
                s_kk[cnt]  = kh*4 + kw;
                s_n[cnt]   = g_seln[pix];
                cnt++;
            }
        }
        s_cnt = cnt;
    }
    __syncthreads();
    int cnt = s_cnt;
    if (tid < 128) {
        int s = tid >> 5, t = tid & 31;
        if (s < cnt && t < s_n[s]) {
            s_ch[s][t] = g_selc[s_pix[s]*30 + t];
            s_cf[s][t] = g_self[s_pix[s]*30 + t];
        }
    }
    __syncthreads();

    int t2 = tid;              // co pair index: co = 2*t2, 2*t2+1
    if (t2 < 150) {
        float ax = 0.f, ay = 0.f;
        const __half2* wtab = (const __half2*)g_wl1h;
        for (int s = 0; s < cnt; s++) {
            int kk = s_kk[s];
            int ns = s_n[s];
            #pragma unroll 4
            for (int t = 0; t < ns; t++) {
                int c = (int)s_ch[s][t];
                float cf = s_cf[s][t];
                float2 wv = __half22float2(wtab[(c*16 + kk)*150 + t2]);
                ax = fmaf(cf, wv.x, ax);
                ay = fmaf(cf, wv.y, ay);
            }
        }
        int co = 2*t2;
        float2 o;
        o.x = fmaxf(ax + b1[co],   0.f);
        o.y = fmaxf(ay + b1[co+1], 0.f);
        *(float2*)&g_y1[((size_t)(b*1156 + oy*34 + ox))*C1 + co] = o;
    }
}

// ---------------- conv2 (dense 300->100 3x3 transpose, f32x2 FMA) ----------------
#define CH2 30
__global__ __launch_bounds__(256) void k_conv2(const float* __restrict__ b2) {
    __shared__ __align__(16) float sw[CH2*3*C2];   // [c1l][dx][c2]
    __shared__ float sy[38*(CH2+1)];               // [ix+2][c1l], zero-padded rows

    int oy  = blockIdx.x;
    int b   = blockIdx.y;
    int tid = threadIdx.x;
    int cg  = tid % 25;       // c2 group
    int og  = tid / 25;       // ox group (active og<9)
    bool active = (tid < 225);
    int c2b = cg*4, ox0 = og*4;

    unsigned long long acc2[2][4];
    #pragma unroll
    for (int p = 0; p < 2; p++)
        #pragma unroll
        for (int j = 0; j < 4; j++) acc2[p][j] = 0ULL;

    for (int dy = 0; dy < 3; dy++) {
        int iy = oy - dy;
        if (iy < 0 || iy >= 34) continue;
        for (int c0 = 0; c0 < C1; c0 += CH2) {
            __syncthreads();
            // zero pad rows (ix+2 in {0,1,36,37})
            for (int i = tid; i < 4*(CH2+1); i += 256) {
                int r = i / (CH2+1), cl = i % (CH2+1);
                int row = (r < 2) ? r : r + 34;
                sy[row*(CH2+1) + cl] = 0.f;
            }
            for (int i = tid; i < 34*CH2; i += 256) {
                int ix = i / CH2, cl = i % CH2;
                sy[(ix+2)*(CH2+1) + cl] =
                    g_y1[((size_t)(b*1156 + iy*34 + ix))*C1 + c0 + cl];
            }
            for (int i = tid; i < CH2*3*C2; i += 256) {
                int c2 = i % C2;
                int t  = i / C2;
                int dx = t % 3;
                int c1l = t / 3;
                sw[i] = g_w2m[((dy*3 + dx)*C1 + c0 + c1l)*C2 + c2];
            }
            __syncthreads();
            if (active) {
                for (int c1l = 0; c1l < CH2; c1l++) {
                    unsigned long long ym[6];
                    #pragma unroll
                    for (int k = 0; k < 6; k++)
                        ym[k] = pk2(sy[(ox0 + k)*(CH2+1) + c1l]);
                    #pragma unroll
                    for (int dx = 0; dx < 3; dx++) {
                        const double* wp =
                            (const double*)(sw + (c1l*3 + dx)*C2 + c2b);
                        unsigned long long wlo = __double_as_longlong(wp[0]);
                        unsigned long long whi = __double_as_longlong(wp[1]);
                        #pragma unroll
                        for (int j = 0; j < 4; j++) {
                            fma2(acc2[0][j], ym[2 + j - dx], wlo);
                            fma2(acc2[1][j], ym[2 + j - dx], whi);
                        }
                    }
                }
            }
        }
    }
    if (active) {
        float bb0 = b2[c2b], bb1 = b2[c2b+1], bb2v = b2[c2b+2], bb3 = b2[c2b+3];
        #pragma unroll
        for (int j = 0; j < 4; j++) {
            float2 lo = upk(acc2[0][j]);
            float2 hi = upk(acc2[1][j]);
            float4 o;
            o.x = fmaxf(lo.x + bb0,  0.f);
            o.y = fmaxf(lo.y + bb1,  0.f);
            o.z = fmaxf(hi.x + bb2v, 0.f);
            o.w = fmaxf(hi.y + bb3,  0.f);
            *(float4*)&g_y2[((size_t)(b*36 + oy)*36 + (ox0+j))*C2 + c2b] = o;
        }
    }
}

// ---------------- conv3 (100->3 3x3 transpose) + ReLU + center crop ----------------
__global__ __launch_bounds__(96) void k_conv3(const float* __restrict__ b3,
                                              float* __restrict__ out) {
    __shared__ float s_y2[3*35*50];
    __shared__ float s_w3[9*C2*3];

    int u   = blockIdx.x;   // output row in crop
    int b   = blockIdx.y;
    int tid = threadIdx.x;  // 96
    int v   = tid % 32;
    int c3  = tid / 32;

    for (int i = tid; i < 9*C2*3; i += 96) s_w3[i] = g_w3m[i];

    float acc = 0.f;
    for (int c0 = 0; c0 < C2; c0 += 50) {
        __syncthreads();
        for (int i = tid; i < 3*35*50; i += 96) {
            int cl = i % 50;
            int t  = i / 50;
            int ix = t % 35;
            int r  = t / 35;
            s_y2[i] = g_y2[((size_t)(b*36 + (u+1+r))*36 + (ix+1))*C2 + c0 + cl];
        }
        __syncthreads();
        for (int dy = 0; dy < 3; dy++) {
            int r = 2 - dy;
            #pragma unroll
            for (int dx = 0; dx < 3; dx++) {
                int col = v + 2 - dx;
                const float* yrow = s_y2 + (r*35 + col)*50;
                const float* wrow = s_w3 + ((dy*3 + dx)*C2 + c0)*3 + c3;
                #pragma unroll 10
                for (int c = 0; c < 50; c++) acc += yrow[c] * wrow[c*3];
            }
        }
    }
    out[((b*3 + c3)*32 + u)*32 + v] = fmaxf(acc + b3[c3], 0.f);
}

// ---------------- launch ----------------
extern "C" void kernel_launch(void* const* d_in, const int* in_sizes, int n_in,
                              void* d_out, int out_size) {
    const float* x    = (const float*)d_in[0];
    const float* phi  = (const float*)d_in[1];
    const float* jump = (const float*)d_in[2];
    const float* w1   = (const float*)d_in[3];
    const float* b1   = (const float*)d_in[4];
    const float* w2   = (const float*)d_in[5];
    const float* b2   = (const float*)d_in[6];
    const float* w3   = (const float*)d_in[7];
    const float* b3   = (const float*)d_in[8];
    float* out = (float*)d_out;

    // order chosen so ncu's sampled slots land on heavy kernels
    k_transpose<<<dim3(16, 8, NB), dim3(32, 32)>>>(x);
    k_l1<<<1, 512>>>(phi);
    k_wl1<<<(NC*16*C1 + 255)/256, 256>>>(w1);
    k_topk<<<4096, 256>>>(jump);
    k_w2m<<<(9*C1*C2 + 255)/256, 256>>>(w2);
    k_conv1<<<dim3(34*34, NB), 160>>>(b1);
    k_conv2<<<dim3(36, NB), 256>>>(b2);
    k_w3m<<<(9*C2*3 + 255)/256, 256>>>(w3);
    k_conv3<<<dim3(32, NB), 96>>>(b3, out);
}

// round 6
// speedup vs baseline: 4.7325x; 3.9301x over previous
#include <cuda_runtime.h>
#include <cuda_fp16.h>
#include <cstdint>

#define NB 128
#define NC 500
#define HWD 16
#define HW 256
#define NPIX (NB*HW)          // 32768
#define C1 300
#define C1P 320               // padded channels for fp16 NHWC y1
#define C2 100
#define NTC 112               // padded N for tensor-core conv2 (14 n8-tiles)

// ---------------- device scratch (no allocations allowed) ----------------
__device__ float  g_l1[NC];
__device__ __half g_wl1h[NC*16*C1];       // [c][kk][co] fp16, pre-scaled by l1
__device__ float  g_xt[(size_t)NPIX*NC];  // [pix][c]
__device__ int    g_seln[NPIX];
__device__ short  g_selc[NPIX*30];
__device__ float  g_self[NPIX*30];
__device__ __half g_y1h[(size_t)NB*34*34*C1P];  // NHWC fp16, padded to 320
__device__ __half g_w2h[9*NTC*C1P];             // [slab][c2p][c1p] fp16
__device__ float  g_y2[(size_t)NB*36*36*C2];    // NHWC f32
__device__ float  g_w3m[9*C2*3];                // [dy][dx][c1][c3]

// ================= baseline-PTX helpers =================
__device__ __forceinline__ uint32_t smem_u32(const void* p) {
    uint32_t a;
    asm("{ .reg .u64 t; cvta.to.shared.u64 t, %1; cvt.u32.u64 %0, t; }"
        : "=r"(a) : "l"(p));
    return a;
}
#define SWZ128(x) ((x) ^ (((x) >> 3) & 0x70))

__device__ __forceinline__ void cpa16(uint32_t dst, const void* src, int sz) {
    asm volatile("cp.async.cg.shared.global [%0], [%1], 16, %2;"
                 :: "r"(dst), "l"(src), "r"(sz));
}
__device__ __forceinline__ void cpa_commit() {
    asm volatile("cp.async.commit_group;");
}
__device__ __forceinline__ void ldsm4(uint32_t* r, uint32_t addr) {
    asm volatile("ldmatrix.sync.aligned.m8n8.x4.shared.b16 {%0,%1,%2,%3}, [%4];"
        : "=r"(r[0]), "=r"(r[1]), "=r"(r[2]), "=r"(r[3]) : "r"(addr));
}
__device__ __forceinline__ void mma16816(float* c, const uint32_t* a,
                                         uint32_t b0, uint32_t b1) {
    asm volatile("mma.sync.aligned.m16n8k16.row.col.f32.f16.f16.f32 "
        "{%0,%1,%2,%3}, {%4,%5,%6,%7}, {%8,%9}, {%0,%1,%2,%3};"
        : "+f"(c[0]), "+f"(c[1]), "+f"(c[2]), "+f"(c[3])
        : "r"(a[0]), "r"(a[1]), "r"(a[2]), "r"(a[3]), "r"(b0), "r"(b1));
}

// ---------------- fused l1 + wl1h ----------------
__global__ __launch_bounds__(256) void k_wl1f(const float* __restrict__ phi,
                                              const float* __restrict__ w1) {
    __shared__ float red[256];
    int c = blockIdx.x;
    int tid = threadIdx.x;
    float s = 0.f;
    for (int d = tid; d < 192; d += 256) s += fabsf(phi[d*NC + c]);
    red[tid] = s;
    __syncthreads();
    for (int off = 128; off; off >>= 1) {
        if (tid < off) red[tid] += red[tid + off];
        __syncthreads();
    }
    float l1 = red[0] + 1e-12f;
    if (tid == 0) g_l1[c] = l1;
    for (int i = tid; i < 16*C1; i += 256) {
        int kk = i / C1, co = i % C1;
        g_wl1h[(c*16 + kk)*C1 + co] = __float2half(l1 * w1[(c*C1 + co)*16 + kk]);
    }
}

// ---------------- w2h[slab][c2p][c1p] fp16 ----------------
__global__ void k_w2h(const float* __restrict__ w2) {
    int e = blockIdx.x*256 + threadIdx.x;
    if (e >= 9*NTC*C1P) return;
    int c1 = e % C1P;
    int t  = e / C1P;
    int c2 = t % NTC;
    int dd = t / NTC;
    int dy = dd / 3, dx = dd % 3;
    float v = (c1 < C1 && c2 < C2) ? w2[((c1*C2 + c2)*3 + dy)*3 + dx] : 0.f;
    g_w2h[e] = __float2half(v);
}

// ---------------- w3m[dy][dx][c1][c3] ----------------
__global__ void k_w3m(const float* __restrict__ w3) {
    int e = blockIdx.x*256 + threadIdx.x;
    if (e >= 9*C2*3) return;
    int c3 = e % 3;
    int t  = e / 3;
    int c1 = t % C2;
    int dd = t / C2;
    int dy = dd / 3, dx = dd % 3;
    g_w3m[e] = w3[((c1*3 + c3)*3 + dy)*3 + dx];
}

// ---------------- transpose x [B][C][HW] -> xt [B][HW][C] ----------------
__global__ void k_transpose(const float* __restrict__ x) {
    __shared__ float tile[32][33];
    int b  = blockIdx.z;
    int c0 = blockIdx.x * 32;
    int h0 = blockIdx.y * 32;
    int tx = threadIdx.x, ty = threadIdx.y;
    int c = c0 + ty, hw = h0 + tx;
    if (c < NC) tile[ty][tx] = x[((size_t)b*NC + c)*HW + hw];
    __syncthreads();
    c = c0 + tx; hw = h0 + ty;
    if (c < NC) g_xt[((size_t)b*HW + hw)*NC + c] = tile[tx][ty];
}

// ---------------- top-30 + saturation -> sparse (channel, coef) ----------------
__global__ void k_topk(const float* __restrict__ jump_ptr) {
    int gwarp = (blockIdx.x * blockDim.x + threadIdx.x) >> 5;
    int lane  = threadIdx.x & 31;
    const float* xr = g_xt + (size_t)gwarp * NC;

    float v[16];
    #pragma unroll
    for (int t = 0; t < 16; t++) {
        int c = lane + t*32;
        v[t] = (c < NC) ? xr[c] : 0.f;
    }
    float jump = *jump_ptr;
    unsigned selmask = 0;
    int n = 0;

    for (int it = 0; it < 30; it++) {
        float ba = -1.f; int bi = 0x7fffffff;
        #pragma unroll
        for (int t = 0; t < 16; t++) {
            int c = lane + t*32;
            if (c < NC && !((selmask >> t) & 1u)) {
                float a = fabsf(v[t]);
                if (a > ba || (a == ba && c < bi)) { ba = a; bi = c; }
            }
        }
        #pragma unroll
        for (int off = 16; off; off >>= 1) {
            float oa = __shfl_xor_sync(0xffffffffu, ba, off);
            int   oi = __shfl_xor_sync(0xffffffffu, bi, off);
            if (oa > ba || (oa == ba && oi < bi)) { ba = oa; bi = oi; }
        }
        if (lane == (bi & 31)) selmask |= 1u << (bi >> 5);
        float xv = xr[bi];
        float l1c = g_l1[bi];
        float r = xv / l1c;
        float rm = r - jump, rp = r + jump;
        float coef = 0.5f * ((float)((rm > 0.f) - (rm < 0.f)) +
                             (float)((rp > 0.f) - (rp < 0.f)));
        if (coef != 0.f) {
            if (lane == 0) {
                g_selc[gwarp*30 + n] = (short)bi;
                g_self[gwarp*30 + n] = coef;
            }
            n++;
        }
    }
    if (lane == 0) g_seln[gwarp] = n;
}

// ---------------- conv1 (sparse gather, fp16 table) -> y1h fp16 NHWC/320 ----------------
__global__ __launch_bounds__(160) void k_conv1(const float* __restrict__ b1) {
    __shared__ int   s_cnt;
    __shared__ int   s_pix[4], s_kk[4], s_n[4];
    __shared__ short s_ch[4][32];
    __shared__ float s_cf[4][32];

    int b   = blockIdx.y;
    int oy  = blockIdx.x / 34;
    int ox  = blockIdx.x % 34;
    int tid = threadIdx.x;

    if (tid == 0) {
        int cnt = 0;
        int p = oy & 1, q = ox & 1;
        for (int kh = p; kh < 4; kh += 2) {
            int iy2 = oy - kh; if (iy2 < 0) continue;
            int iy = iy2 >> 1; if (iy >= HWD) continue;
            for (int kw = q; kw < 4; kw += 2) {
                int ix2 = ox - kw; if (ix2 < 0) continue;
                int ix = ix2 >> 1; if (ix >= HWD) continue;
                int pix = (b*HWD + iy)*HWD + ix;
                s_pix[cnt] = pix;
                s_kk[cnt]  = kh*4 + kw;
                s_n[cnt]   = g_seln[pix];
                cnt++;
            }
        }
        s_cnt = cnt;
    }
    __syncthreads();
    int cnt = s_cnt;
    if (tid < 128) {
        int s = tid >> 5, t = tid & 31;
        if (s < cnt && t < s_n[s]) {
            s_ch[s][t] = g_selc[s_pix[s]*30 + t];
            s_cf[s][t] = g_self[s_pix[s]*30 + t];
        }
    }
    __syncthreads();

    size_t obase = ((size_t)(b*1156 + oy*34 + ox))*C1P;
    int t2 = tid;
    if (t2 < 150) {
        float ax = 0.f, ay = 0.f;
        const __half2* wtab = (const __half2*)g_wl1h;
        for (int s = 0; s < cnt; s++) {
            int kk = s_kk[s];
            int ns = s_n[s];
            #pragma unroll 4
            for (int t = 0; t < ns; t++) {
                int c = (int)s_ch[s][t];
                float cf = s_cf[s][t];
                float2 wv = __half22float2(wtab[(c*16 + kk)*150 + t2]);
                ax = fmaf(cf, wv.x, ax);
                ay = fmaf(cf, wv.y, ay);
            }
        }
        int co = 2*t2;
        float ox2 = fmaxf(ax + b1[co],   0.f);
        float oy2 = fmaxf(ay + b1[co+1], 0.f);
        ((__half2*)(g_y1h + obase))[t2] = __floats2half2_rn(ox2, oy2);
    } else {
        ((__half2*)(g_y1h + obase))[t2] = __floats2half2_rn(0.f, 0.f);
    }
}

// ---------------- conv2: fp16 HMMA implicit GEMM (mma.sync, baseline PTX) ----
// M=128 pixels/CTA, N=112 (c2 padded), K = 9 slabs * 320 ch, chunks of 64
// stage layout: A 128x64 fp16 (16KB, SW128) + B 112x64 fp16 (14KB, SW128)
#define STAGE_BYTES 30720
__global__ __launch_bounds__(256) void k_conv2_mma(const float* __restrict__ b2) {
    extern __shared__ char dsm[];
    uint32_t smu = smem_u32(dsm);

    int tid = threadIdx.x;
    int wid = tid >> 5;
    int lane = tid & 31;
    int b  = blockIdx.y;
    int p0 = blockIdx.x * 128;

    float acc[14][4];
    #pragma unroll
    for (int i = 0; i < 14; i++)
        #pragma unroll
        for (int j = 0; j < 4; j++) acc[i][j] = 0.f;

    int arow  = wid*16 + (lane & 15);
    int acolb = (lane >> 4) * 16;
    int bn  = (lane & 7) + ((lane >> 4) & 1) * 8;
    int bkb = ((lane >> 3) & 1) * 16;

    auto issue = [&](int i) {
        int s = i & 1;
        int slab = i / 5;
        int c0 = (i - slab*5) * 64;
        int dy = slab / 3, dx = slab - dy*3;
        uint32_t abase = smu + (uint32_t)s * STAGE_BYTES;
        uint32_t bbase = abase + 16384u;
        #pragma unroll
        for (int k = 0; k < 4; k++) {
            int idx = tid + k*256;
            int r = idx >> 3, j = idx & 7;
            int p = p0 + r;
            int oy = p / 36, ox = p - oy*36;
            int iy = oy - dy, ix = ox - dx;
            bool val = (p < 1296) && (iy >= 0) && (iy < 34) && (ix >= 0) && (ix < 34);
            size_t goff = val ? ((size_t)((b*34 + iy)*34 + ix)*C1P + c0 + j*8) : 0;
            cpa16(abase + SWZ128(r*128 + j*16), g_y1h + goff, val ? 16 : 0);
        }
        const __half* wbase = g_w2h + slab*(NTC*C1P) + c0;
        #pragma unroll
        for (int k = 0; k < 4; k++) {
            int idx = tid + k*256;
            if (idx < 896) {
                int r = idx >> 3, j = idx & 7;
                cpa16(bbase + SWZ128(r*128 + j*16), wbase + r*C1P + j*8, 16);
            }
        }
        cpa_commit();
    };

    auto compute = [&](int s) {
        uint32_t abase = smu + (uint32_t)s * STAGE_BYTES;
        uint32_t bbase = abase + 16384u;
        uint32_t afr[4][4];
        #pragma unroll
        for (int ks = 0; ks < 4; ks++)
            ldsm4(afr[ks], abase + SWZ128(arow*128 + ks*32 + acolb));
        #pragma unroll
        for (int np = 0; np < 7; np++) {
            #pragma unroll
            for (int ks = 0; ks < 4; ks++) {
                uint32_t bf[4];
                ldsm4(bf, bbase + SWZ128((np*16 + bn)*128 + ks*32 + bkb));
                mma16816(acc[np*2],     afr[ks], bf[0], bf[1]);
                mma16816(acc[np*2 + 1], afr[ks], bf[2], bf[3]);
            }
        }
    };

    issue(0);
    issue(1);
    for (int i = 0; i < 45; i++) {
        if (i <= 42) asm volatile("cp.async.wait_group 1;" ::: "memory");
        else         asm volatile("cp.async.wait_group 0;" ::: "memory");
        __syncthreads();
        compute(i & 1);
        __syncthreads();
        if (i <= 42) issue(i + 2);
    }

    // epilogue: bias + relu + store f32 NHWC
    int g  = lane >> 2;
    int qp = (lane & 3) * 2;
    int r0 = p0 + wid*16 + g;
    #pragma unroll
    for (int nt = 0; nt < 14; nt++) {
        int n = nt*8 + qp;
        if (n < 100) {
            float b0v = b2[n], b1v = b2[n + 1];
            if (r0 < 1296) {
                float2 o;
                o.x = fmaxf(acc[nt][0] + b0v, 0.f);
                o.y = fmaxf(acc[nt][1] + b1v, 0.f);
                *(float2*)&g_y2[((size_t)b*1296 + r0)*C2 + n] = o;
            }
            if (r0 + 8 < 1296) {
                float2 o;
                o.x = fmaxf(acc[nt][2] + b0v, 0.f);
                o.y = fmaxf(acc[nt][3] + b1v, 0.f);
                *(float2*)&g_y2[((size_t)b*1296 + r0 + 8)*C2 + n] = o;
            }
        }
    }
}

// ---------------- conv3 (100->3 3x3 transpose) + ReLU + center crop ----------------
__global__ __launch_bounds__(96) void k_conv3(const float* __restrict__ b3,
                                              float* __restrict__ out) {
    __shared__ float s_y2[3*35*50];
    __shared__ float s_w3[9*C2*3];

    int u   = blockIdx.x;
    int b   = blockIdx.y;
    int tid = threadIdx.x;
    int v   = tid % 32;
    int c3  = tid / 32;

    for (int i = tid; i < 9*C2*3; i += 96) s_w3[i] = g_w3m[i];

    float acc = 0.f;
    for (int c0 = 0; c0 < C2; c0 += 50) {
        __syncthreads();
        for (int i = tid; i < 3*35*50; i += 96) {
            int cl = i % 50;
            int t  = i / 50;
            int ix = t % 35;
            int r  = t / 35;
            s_y2[i] = g_y2[((size_t)(b*36 + (u+1+r))*36 + (ix+1))*C2 + c0 + cl];
        }
        __syncthreads();
        for (int dy = 0; dy < 3; dy++) {
            int r = 2 - dy;
            #pragma unroll
            for (int dx = 0; dx < 3; dx++) {
                int col = v + 2 - dx;
                const float* yrow = s_y2 + (r*35 + col)*50;
                const float* wrow = s_w3 + ((dy*3 + dx)*C2 + c0)*3 + c3;
                #pragma unroll 10
                for (int c = 0; c < 50; c++) acc += yrow[c] * wrow[c*3];
            }
        }
    }
    out[((b*3 + c3)*32 + u)*32 + v] = fmaxf(acc + b3[c3], 0.f);
}

// ---------------- launch ----------------
extern "C" void kernel_launch(void* const* d_in, const int* in_sizes, int n_in,
                              void* d_out, int out_size) {
    const float* x    = (const float*)d_in[0];
    const float* phi  = (const float*)d_in[1];
    const float* jump = (const float*)d_in[2];
    const float* w1   = (const float*)d_in[3];
    const float* b1   = (const float*)d_in[4];
    const float* w2   = (const float*)d_in[5];
    const float* b2   = (const float*)d_in[6];
    const float* w3   = (const float*)d_in[7];
    const float* b3   = (const float*)d_in[8];
    float* out = (float*)d_out;

    cudaFuncSetAttribute(k_conv2_mma, cudaFuncAttributeMaxDynamicSharedMemorySize,
                         2*STAGE_BYTES);

    k_wl1f<<<NC, 256>>>(phi, w1);                       // 0
    k_transpose<<<dim3(16, 8, NB), dim3(32, 32)>>>(x);  // 1
    k_topk<<<4096, 256>>>(jump);                        // 2
    k_conv1<<<dim3(34*34, NB), 160>>>(b1);              // 3  <- profiled slot
    k_w2h<<<(9*NTC*C1P + 255)/256, 256>>>(w2);          // 4
    k_conv2_mma<<<dim3(11, NB), 256, 2*STAGE_BYTES>>>(b2); // 5
    k_w3m<<<(9*C2*3 + 255)/256, 256>>>(w3);             // 6
    k_conv3<<<dim3(32, NB), 96>>>(b3, out);             // 7
}

// round 8
// speedup vs baseline: 5.9800x; 1.2636x over previous
#include <cuda_runtime.h>
#include <cuda_fp16.h>
#include <cstdint>

#define NB 128
#define NC 500
#define HWD 16
#define HW 256
#define NPIX (NB*HW)          // 32768
#define C1 300
#define C1P 320               // padded channels for fp16 NHWC y1
#define C2 100
#define NTC 112               // padded N for tensor-core conv2 (14 n8-tiles)

// ---------------- device scratch (no allocations allowed) ----------------
__device__ float  g_l1[NC];
__device__ __half g_wl1h[NC*16*C1];       // [c][kk][co] fp16, pre-scaled by l1
__device__ int    g_seln[NPIX];
__device__ short  g_selc[NPIX*30];
__device__ float  g_self[NPIX*30];
__device__ __half g_y1h[(size_t)NB*34*34*C1P];  // NHWC fp16, padded to 320
__device__ __half g_w2h[9*NTC*C1P];             // [slab][c2p][c1p] fp16
__device__ float  g_y2[(size_t)NB*36*36*C2];    // NHWC f32
__device__ float  g_w3m[9*C2*3];                // [dy][dx][c1][c3]

// ================= baseline-PTX helpers =================
__device__ __forceinline__ uint32_t smem_u32(const void* p) {
    uint32_t a;
    asm("{ .reg .u64 t; cvta.to.shared.u64 t, %1; cvt.u32.u64 %0, t; }"
        : "=r"(a) : "l"(p));
    return a;
}
#define SWZ128(x) ((x) ^ (((x) >> 3) & 0x70))

__device__ __forceinline__ void cpa16(uint32_t dst, const void* src, int sz) {
    asm volatile("cp.async.cg.shared.global [%0], [%1], 16, %2;"
                 :: "r"(dst), "l"(src), "r"(sz));
}
__device__ __forceinline__ void cpa_commit() {
    asm volatile("cp.async.commit_group;");
}
__device__ __forceinline__ void ldsm4(uint32_t* r, uint32_t addr) {
    asm volatile("ldmatrix.sync.aligned.m8n8.x4.shared.b16 {%0,%1,%2,%3}, [%4];"
        : "=r"(r[0]), "=r"(r[1]), "=r"(r[2]), "=r"(r[3]) : "r"(addr));
}
__device__ __forceinline__ void mma16816(float* c, const uint32_t* a,
                                         uint32_t b0, uint32_t b1) {
    asm volatile("mma.sync.aligned.m16n8k16.row.col.f32.f16.f16.f32 "
        "{%0,%1,%2,%3}, {%4,%5,%6,%7}, {%8,%9}, {%0,%1,%2,%3};"
        : "+f"(c[0]), "+f"(c[1]), "+f"(c[2]), "+f"(c[3])
        : "r"(a[0]), "r"(a[1]), "r"(a[2]), "r"(a[3]), "r"(b0), "r"(b1));
}

// ---------------- consolidated prep: l1 + wl1h + w2h + w3m ----------------
#define W2H_BLKS ((9*NTC*C1P + 255)/256)   // 1260
#define W3M_BLKS ((9*C2*3 + 255)/256)      // 11
__global__ __launch_bounds__(256) void k_prep(const float* __restrict__ phi,
                                              const float* __restrict__ w1,
                                              const float* __restrict__ w2,
                                              const float* __restrict__ w3) {
    int blk = blockIdx.x;
    int tid = threadIdx.x;
    if (blk < NC) {
        __shared__ float red[256];
        int c = blk;
        float s = 0.f;
        for (int d = tid; d < 192; d += 256) s += fabsf(phi[d*NC + c]);
        red[tid] = s;
        __syncthreads();
        for (int off = 128; off; off >>= 1) {
            if (tid < off) red[tid] += red[tid + off];
            __syncthreads();
        }
        float l1 = red[0] + 1e-12f;
        if (tid == 0) g_l1[c] = l1;
        for (int i = tid; i < 16*C1; i += 256) {
            int kk = i / C1, co = i % C1;
            g_wl1h[(c*16 + kk)*C1 + co] = __float2half(l1 * w1[(c*C1 + co)*16 + kk]);
        }
    } else if (blk < NC + W2H_BLKS) {
        int e = (blk - NC)*256 + tid;
        if (e < 9*NTC*C1P) {
            int c1 = e % C1P;
            int t  = e / C1P;
            int c2 = t % NTC;
            int dd = t / NTC;
            int dy = dd / 3, dx = dd % 3;
            float v = (c1 < C1 && c2 < C2) ? w2[((c1*C2 + c2)*3 + dy)*3 + dx] : 0.f;
            g_w2h[e] = __float2half(v);
        }
    } else {
        int e = (blk - NC - W2H_BLKS)*256 + tid;
        if (e < 9*C2*3) {
            int c3 = e % 3;
            int t  = e / 3;
            int c1 = t % C2;
            int dd = t / C2;
            int dy = dd / 3, dx = dd % 3;
            g_w3m[e] = w3[((c1*3 + c3)*3 + dy)*3 + dx];
        }
    }
}

// ---------------- fused transpose + top-30 + saturation ----------------
// block: 32 pixels of one batch staged into smem [500][33]; 8 warps x 4 pixels
#define TOPK_SMEM ((NC*33 + NC)*4)
__global__ __launch_bounds__(256) void k_topk(const float* __restrict__ x,
                                              const float* __restrict__ jump_ptr) {
    extern __shared__ float sm[];
    float* sx  = sm;            // [500][33]
    float* sl1 = sm + NC*33;    // [500]

    int b   = blockIdx.y;
    int hw0 = blockIdx.x * 32;
    int tid = threadIdx.x;
    const float* xb = x + ((size_t)b*NC)*HW + hw0;

    for (int i = tid; i < NC*8; i += 256) {
        int c = i >> 3, j = i & 7;
        float4 v = *(const float4*)(xb + c*HW + j*4);
        float* d = sx + c*33 + j*4;
        d[0] = v.x; d[1] = v.y; d[2] = v.z; d[3] = v.w;
    }
    for (int i = tid; i < NC; i += 256) sl1[i] = g_l1[i];
    __syncthreads();

    float jump = *jump_ptr;
    int wid = tid >> 5, lane = tid & 31;

    for (int q = 0; q < 4; q++) {
        int p   = wid*4 + q;
        int pix = b*HW + hw0 + p;

        unsigned u[16];
        #pragma unroll
        for (int t = 0; t < 16; t++) {
            int c = lane + t*32;
            u[t] = (c < NC) ? (__float_as_uint(sx[c*33 + p]) & 0x7fffffffu) : 0u;
        }

        int n = 0;
        for (int it = 0; it < 30; it++) {
            // local max: tree of uint max (depth 4)
            unsigned a0 = max(u[0], u[1]),  a1 = max(u[2], u[3]);
            unsigned a2 = max(u[4], u[5]),  a3 = max(u[6], u[7]);
            unsigned a4 = max(u[8], u[9]),  a5 = max(u[10], u[11]);
            unsigned a6 = max(u[12], u[13]), a7 = max(u[14], u[15]);
            unsigned b0 = max(a0, a1), b1 = max(a2, a3);
            unsigned b2 = max(a4, a5), b3 = max(a6, a7);
            unsigned lm = max(max(b0, b1), max(b2, b3));

            unsigned gm = __reduce_max_sync(0xffffffffu, lm);
            unsigned ball = __ballot_sync(0xffffffffu, lm == gm);
            int leader = __ffs(ball) - 1;
            int c_sel = 0;
            if (lane == leader) {
                int mi = 0;
                #pragma unroll
                for (int t = 15; t >= 0; t--)
                    if (u[t] == gm) { mi = t; u[t] = 0u; }
                c_sel = lane + mi*32;
            }
            c_sel = __shfl_sync(0xffffffffu, c_sel, leader);

            float xv = sx[c_sel*33 + p];
            float th = jump * sl1[c_sel];
            float coef = 0.5f * ((float)((xv > th) - (xv < th)) +
                                 (float)((xv > -th) - (xv < -th)));
            if (coef != 0.f) {
                if (lane == 0) {
                    g_selc[pix*30 + n] = (short)c_sel;
                    g_self[pix*30 + n] = coef;
                }
                n++;
            }
        }
        if (lane == 0) g_seln[pix] = n;
    }
}

// ---------------- conv1 (sparse gather, fp16 table) -> y1h fp16 NHWC/320 ----------------
__global__ __launch_bounds__(160) void k_conv1(const float* __restrict__ b1) {
    __shared__ int   s_cnt;
    __shared__ int   s_pix[4], s_kk[4], s_n[4];
    __shared__ short s_ch[4][32];
    __shared__ float s_cf[4][32];

    int b   = blockIdx.y;
    int oy  = blockIdx.x / 34;
    int ox  = blockIdx.x % 34;
    int tid = threadIdx.x;

    if (tid == 0) {
        int cnt = 0;
        int p = oy & 1, q = ox & 1;
        for (int kh = p; kh < 4; kh += 2) {
            int iy2 = oy - kh; if (iy2 < 0) continue;
            int iy = iy2 >> 1; if (iy >= HWD) continue;
            for (int kw = q; kw < 4; kw += 2) {
                int ix2 = ox - kw; if (ix2 < 0) continue;
                int ix = ix2 >> 1; if (ix >= HWD) continue;
                int pix = (b*HWD + iy)*HWD + ix;
                s_pix[cnt] = pix;
                s_kk[cnt]  = kh*4 + kw;
                s_n[cnt]   = g_seln[pix];
                cnt++;
            }
        }
        s_cnt = cnt;
    }
    __syncthreads();
    int cnt = s_cnt;
    if (tid < 128) {
        int s = tid >> 5, t = tid & 31;
        if (s < cnt && t < s_n[s]) {
            s_ch[s][t] = g_selc[s_pix[s]*30 + t];
            s_cf[s][t] = g_self[s_pix[s]*30 + t];
        }
    }
    __syncthreads();

    size_t obase = ((size_t)(b*1156 + oy*34 + ox))*C1P;
    int t2 = tid;
    if (t2 < 150) {
        float ax = 0.f, ay = 0.f;
        const __half2* wtab = (const __half2*)g_wl1h;
        for (int s = 0; s < cnt; s++) {
            int kk = s_kk[s];
            int ns = s_n[s];
            #pragma unroll 4
            for (int t = 0; t < ns; t++) {
                int c = (int)s_ch[s][t];
                float cf = s_cf[s][t];
                float2 wv = __half22float2(wtab[(c*16 + kk)*150 + t2]);
                ax = fmaf(cf, wv.x, ax);
                ay = fmaf(cf, wv.y, ay);
            }
        }
        int co = 2*t2;
        float ox2 = fmaxf(ax + b1[co],   0.f);
        float oy2 = fmaxf(ay + b1[co+1], 0.f);
        ((__half2*)(g_y1h + obase))[t2] = __floats2half2_rn(ox2, oy2);
    } else {
        ((__half2*)(g_y1h + obase))[t2] = __floats2half2_rn(0.f, 0.f);
    }
}

// ---------------- conv2: fp16 HMMA implicit GEMM (mma.sync, baseline PTX) ----
// M=128 pixels/CTA, N=112 (c2 padded), K = 9 slabs * 320 ch, chunks of 64
#define STAGE_BYTES 30720
__global__ __launch_bounds__(256) void k_conv2_mma(const float* __restrict__ b2) {
    extern __shared__ char dsm[];
    uint32_t smu = smem_u32(dsm);

    int tid = threadIdx.x;
    int wid = tid >> 5;
    int lane = tid & 31;
    int b  = blockIdx.y;
    int p0 = blockIdx.x * 128;

    float acc[14][4];
    #pragma unroll
    for (int i = 0; i < 14; i++)
        #pragma unroll
        for (int j = 0; j < 4; j++) acc[i][j] = 0.f;

    int arow  = wid*16 + (lane & 15);
    int acolb = (lane >> 4) * 16;
    int bn  = (lane & 7) + ((lane >> 4) & 1) * 8;
    int bkb = ((lane >> 3) & 1) * 16;

    auto issue = [&](int i) {
        int s = i & 1;
        int slab = i / 5;
        int c0 = (i - slab*5) * 64;
        int dy = slab / 3, dx = slab - dy*3;
        uint32_t abase = smu + (uint32_t)s * STAGE_BYTES;
        uint32_t bbase = abase + 16384u;
        #pragma unroll
        for (int k = 0; k < 4; k++) {
            int idx = tid + k*256;
            int r = idx >> 3, j = idx & 7;
            int p = p0 + r;
            int oy = p / 36, ox = p - oy*36;
            int iy = oy - dy, ix = ox - dx;
            bool val = (p < 1296) && (iy >= 0) && (iy < 34) && (ix >= 0) && (ix < 34);
            size_t goff = val ? ((size_t)((b*34 + iy)*34 + ix)*C1P + c0 + j*8) : 0;
            cpa16(abase + SWZ128(r*128 + j*16), g_y1h + goff, val ? 16 : 0);
        }
        const __half* wbase = g_w2h + slab*(NTC*C1P) + c0;
        #pragma unroll
        for (int k = 0; k < 4; k++) {
            int idx = tid + k*256;
            if (idx < 896) {
                int r = idx >> 3, j = idx & 7;
                cpa16(bbase + SWZ128(r*128 + j*16), wbase + r*C1P + j*8, 16);
            }
        }
        cpa_commit();
    };

    auto compute = [&](int s) {
        uint32_t abase = smu + (uint32_t)s * STAGE_BYTES;
        uint32_t bbase = abase + 16384u;
        uint32_t afr[4][4];
        #pragma unroll
        for (int ks = 0; ks < 4; ks++)
            ldsm4(afr[ks], abase + SWZ128(arow*128 + ks*32 + acolb));
        #pragma unroll
        for (int np = 0; np < 7; np++) {
            #pragma unroll
            for (int ks = 0; ks < 4; ks++) {
                uint32_t bf[4];
                ldsm4(bf, bbase + SWZ128((np*16 + bn)*128 + ks*32 + bkb));
                mma16816(acc[np*2],     afr[ks], bf[0], bf[1]);
                mma16816(acc[np*2 + 1], afr[ks], bf[2], bf[3]);
            }
        }
    };

    issue(0);
    issue(1);
    for (int i = 0; i < 45; i++) {
        if (i <= 42) asm volatile("cp.async.wait_group 1;" ::: "memory");
        else         asm volatile("cp.async.wait_group 0;" ::: "memory");
        __syncthreads();
        compute(i & 1);
        __syncthreads();
        if (i <= 42) issue(i + 2);
    }

    // epilogue: bias + relu + store f32 NHWC
    int g  = lane >> 2;
    int qp = (lane & 3) * 2;
    int r0 = p0 + wid*16 + g;
    #pragma unroll
    for (int nt = 0; nt < 14; nt++) {
        int n = nt*8 + qp;
        if (n < 100) {
            float b0v = b2[n], b1v = b2[n + 1];
            if (r0 < 1296) {
                float2 o;
                o.x = fmaxf(acc[nt][0] + b0v, 0.f);
                o.y = fmaxf(acc[nt][1] + b1v, 0.f);
                *(float2*)&g_y2[((size_t)b*1296 + r0)*C2 + n] = o;
            }
            if (r0 + 8 < 1296) {
                float2 o;
                o.x = fmaxf(acc[nt][2] + b0v, 0.f);
                o.y = fmaxf(acc[nt][3] + b1v, 0.f);
                *(float2*)&g_y2[((size_t)b*1296 + r0 + 8)*C2 + n] = o;
            }
        }
    }
}

// ---------------- conv3 (100->3 3x3 transpose) + ReLU + center crop ----------------
__global__ __launch_bounds__(96) void k_conv3(const float* __restrict__ b3,
                                              float* __restrict__ out) {
    __shared__ float s_y2[3*35*50];
    __shared__ float s_w3[9*C2*3];

    int u   = blockIdx.x;
    int b   = blockIdx.y;
    int tid = threadIdx.x;
    int v   = tid % 32;
    int c3  = tid / 32;

    for (int i = tid; i < 9*C2*3; i += 96) s_w3[i] = g_w3m[i];

    float acc = 0.f;
    for (int c0 = 0; c0 < C2; c0 += 50) {
        __syncthreads();
        for (int i = tid; i < 3*35*50; i += 96) {
            int cl = i % 50;
            int t  = i / 50;
            int ix = t % 35;
            int r  = t / 35;
            s_y2[i] = g_y2[((size_t)(b*36 + (u+1+r))*36 + (ix+1))*C2 + c0 + cl];
        }
        __syncthreads();
        for (int dy = 0; dy < 3; dy++) {
            int r = 2 - dy;
            #pragma unroll
            for (int dx = 0; dx < 3; dx++) {
                int col = v + 2 - dx;
                const float* yrow = s_y2 + (r*35 + col)*50;
                const float* wrow = s_w3 + ((dy*3 + dx)*C2 + c0)*3 + c3;
                #pragma unroll 10
                for (int c = 0; c < 50; c++) acc += yrow[c] * wrow[c*3];
            }
        }
    }
    out[((b*3 + c3)*32 + u)*32 + v] = fmaxf(acc + b3[c3], 0.f);
}

// ---------------- launch ----------------
extern "C" void kernel_launch(void* const* d_in, const int* in_sizes, int n_in,
                              void* d_out, int out_size) {
    const float* x    = (const float*)d_in[0];
    const float* phi  = (const float*)d_in[1];
    const float* jump = (const float*)d_in[2];
    const float* w1   = (const float*)d_in[3];
    const float* b1   = (const float*)d_in[4];
    const float* w2   = (const float*)d_in[5];
    const float* b2   = (const float*)d_in[6];
    const float* w3   = (const float*)d_in[7];
    const float* b3   = (const float*)d_in[8];
    float* out = (float*)d_out;

    cudaFuncSetAttribute(k_conv2_mma, cudaFuncAttributeMaxDynamicSharedMemorySize,
                         2*STAGE_BYTES);
    cudaFuncSetAttribute(k_topk, cudaFuncAttributeMaxDynamicSharedMemorySize,
                         TOPK_SMEM);

    k_prep<<<NC + W2H_BLKS + W3M_BLKS, 256>>>(phi, w1, w2, w3);   // 0
    k_topk<<<dim3(8, NB), 256, TOPK_SMEM>>>(x, jump);             // 1
    k_conv1<<<dim3(34*34, NB), 160>>>(b1);                        // 2
    k_conv2_mma<<<dim3(11, NB), 256, 2*STAGE_BYTES>>>(b2);        // 3  <- profiled slot
    k_conv3<<<dim3(32, NB), 96>>>(b3, out);                       // 4
}

// round 10
// speedup vs baseline: 6.1122x; 1.0221x over previous
#include <cuda_runtime.h>
#include <cuda_fp16.h>
#include <cstdint>

#define NB 128
#define NC 500
#define HWD 16
#define HW 256
#define NPIX (NB*HW)          // 32768
#define C1 300
#define C1P 320               // padded channels for fp16 NHWC y1
#define C2 100
#define NTC 128               // padded N for tensor-core conv2 (16 n8-tiles)

// ---------------- device scratch (no allocations allowed) ----------------
__device__ float  g_l1[NC];
__device__ __half g_wl1h[NC*16*C1];       // [c][kk][co] fp16, pre-scaled by l1
__device__ int    g_seln[NPIX];
__device__ short  g_selc[NPIX*30];
__device__ float  g_self[NPIX*30];
__device__ __half g_y1h[(size_t)NB*34*34*C1P];  // NHWC fp16, padded to 320
__device__ __half g_w2h[9*NTC*C1P];             // [slab][c2p][c1p] fp16
__device__ float  g_y2[(size_t)NB*36*36*C2];    // NHWC f32
__device__ float  g_w3m[9*C2*3];                // [dy][dx][c1][c3]

// ================= baseline-PTX helpers =================
__device__ __forceinline__ uint32_t smem_u32(const void* p) {
    uint32_t a;
    asm("{ .reg .u64 t; cvta.to.shared.u64 t, %1; cvt.u32.u64 %0, t; }"
        : "=r"(a) : "l"(p));
    return a;
}
#define SWZ128(x) ((x) ^ (((x) >> 3) & 0x70))

__device__ __forceinline__ void cpa16(uint32_t dst, const void* src, int sz) {
    asm volatile("cp.async.cg.shared.global [%0], [%1], 16, %2;"
                 :: "r"(dst), "l"(src), "r"(sz));
}
__device__ __forceinline__ void cpa_commit() {
    asm volatile("cp.async.commit_group;");
}
__device__ __forceinline__ void ldsm4(uint32_t* r, uint32_t addr) {
    asm volatile("ldmatrix.sync.aligned.m8n8.x4.shared.b16 {%0,%1,%2,%3}, [%4];"
        : "=r"(r[0]), "=r"(r[1]), "=r"(r[2]), "=r"(r[3]) : "r"(addr));
}
__device__ __forceinline__ void mma16816(float* c, const uint32_t* a,
                                         uint32_t b0, uint32_t b1) {
    asm volatile("mma.sync.aligned.m16n8k16.row.col.f32.f16.f16.f32 "
        "{%0,%1,%2,%3}, {%4,%5,%6,%7}, {%8,%9}, {%0,%1,%2,%3};"
        : "+f"(c[0]), "+f"(c[1]), "+f"(c[2]), "+f"(c[3])
        : "r"(a[0]), "r"(a[1]), "r"(a[2]), "r"(a[3]), "r"(b0), "r"(b1));
}

// ---------------- consolidated prep: l1 + wl1h + w2h + w3m ----------------
#define W2H_BLKS ((9*NTC*C1P + 255)/256)
#define W3M_BLKS ((9*C2*3 + 255)/256)
__global__ __launch_bounds__(256) void k_prep(const float* __restrict__ phi,
                                              const float* __restrict__ w1,
                                              const float* __restrict__ w2,
                                              const float* __restrict__ w3) {
    int blk = blockIdx.x;
    int tid = threadIdx.x;
    if (blk < NC) {
        __shared__ float red[256];
        int c = blk;
        float s = 0.f;
        for (int d = tid; d < 192; d += 256) s += fabsf(phi[d*NC + c]);
        red[tid] = s;
        __syncthreads();
        for (int off = 128; off; off >>= 1) {
            if (tid < off) red[tid] += red[tid + off];
            __syncthreads();
        }
        float l1 = red[0] + 1e-12f;
        if (tid == 0) g_l1[c] = l1;
        for (int i = tid; i < 16*C1; i += 256) {
            int kk = i / C1, co = i % C1;
            g_wl1h[(c*16 + kk)*C1 + co] = __float2half(l1 * w1[(c*C1 + co)*16 + kk]);
        }
    } else if (blk < NC + W2H_BLKS) {
        int e = (blk - NC)*256 + tid;
        if (e < 9*NTC*C1P) {
            int c1 = e % C1P;
            int t  = e / C1P;
            int c2 = t % NTC;
            int dd = t / NTC;
            int dy = dd / 3, dx = dd % 3;
            float v = (c1 < C1 && c2 < C2) ? w2[((c1*C2 + c2)*3 + dy)*3 + dx] : 0.f;
            g_w2h[e] = __float2half(v);
        }
    } else {
        int e = (blk - NC - W2H_BLKS)*256 + tid;
        if (e < 9*C2*3) {
            int c3 = e % 3;
            int t  = e / 3;
            int c1 = t % C2;
            int dd = t / C2;
            int dy = dd / 3, dx = dd % 3;
            g_w3m[e] = w3[((c1*3 + c3)*3 + dy)*3 + dx];
        }
    }
}

// ---------------- fused transpose + top-30 + saturation ----------------
#define TOPK_SMEM ((NC*33 + NC)*4)
__global__ __launch_bounds__(256) void k_topk(const float* __restrict__ x,
                                              const float* __restrict__ jump_ptr) {
    extern __shared__ float sm[];
    float* sx  = sm;            // [500][33]
    float* sl1 = sm + NC*33;    // [500]

    int b   = blockIdx.y;
    int hw0 = blockIdx.x * 32;
    int tid = threadIdx.x;
    const float* xb = x + ((size_t)b*NC)*HW + hw0;

    for (int i = tid; i < NC*8; i += 256) {
        int c = i >> 3, j = i & 7;
        float4 v = *(const float4*)(xb + c*HW + j*4);
        float* d = sx + c*33 + j*4;
        d[0] = v.x; d[1] = v.y; d[2] = v.z; d[3] = v.w;
    }
    for (int i = tid; i < NC; i += 256) sl1[i] = g_l1[i];
    __syncthreads();

    float jump = *jump_ptr;
    int wid = tid >> 5, lane = tid & 31;

    for (int q = 0; q < 4; q++) {
        int p   = wid*4 + q;
        int pix = b*HW + hw0 + p;

        unsigned u[16];
        #pragma unroll
        for (int t = 0; t < 16; t++) {
            int c = lane + t*32;
            u[t] = (c < NC) ? (__float_as_uint(sx[c*33 + p]) & 0x7fffffffu) : 0u;
        }

        int n = 0;
        for (int it = 0; it < 30; it++) {
            unsigned a0 = max(u[0], u[1]),  a1 = max(u[2], u[3]);
            unsigned a2 = max(u[4], u[5]),  a3 = max(u[6], u[7]);
            unsigned a4 = max(u[8], u[9]),  a5 = max(u[10], u[11]);
            unsigned a6 = max(u[12], u[13]), a7 = max(u[14], u[15]);
            unsigned b0 = max(a0, a1), b1 = max(a2, a3);
            unsigned b2 = max(a4, a5), b3 = max(a6, a7);
            unsigned lm = max(max(b0, b1), max(b2, b3));

            unsigned gm = __reduce_max_sync(0xffffffffu, lm);
            unsigned ball = __ballot_sync(0xffffffffu, lm == gm);
            int leader = __ffs(ball) - 1;
            int c_sel = 0;
            if (lane == leader) {
                int mi = 0;
                #pragma unroll
                for (int t = 15; t >= 0; t--)
                    if (u[t] == gm) { mi = t; u[t] = 0u; }
                c_sel = lane + mi*32;
            }
            c_sel = __shfl_sync(0xffffffffu, c_sel, leader);

            float xv = sx[c_sel*33 + p];
            float th = jump * sl1[c_sel];
            float coef = 0.5f * ((float)((xv > th) - (xv < th)) +
                                 (float)((xv > -th) - (xv < -th)));
            if (coef != 0.f) {
                if (lane == 0) {
                    g_selc[pix*30 + n] = (short)c_sel;
                    g_self[pix*30 + n] = coef;
                }
                n++;
            }
        }
        if (lane == 0) g_seln[pix] = n;
    }
}

// ---------------- conv1 (sparse gather, fp16 table) -> y1h fp16 NHWC/320 ----------------
__global__ __launch_bounds__(160) void k_conv1(const float* __restrict__ b1) {
    __shared__ int   s_cnt;
    __shared__ int   s_pix[4], s_kk[4], s_n[4];
    __shared__ short s_ch[4][32];
    __shared__ float s_cf[4][32];

    int b   = blockIdx.y;
    int oy  = blockIdx.x / 34;
    int ox  = blockIdx.x % 34;
    int tid = threadIdx.x;

    if (tid == 0) {
        int cnt = 0;
        int p = oy & 1, q = ox & 1;
        for (int kh = p; kh < 4; kh += 2) {
            int iy2 = oy - kh; if (iy2 < 0) continue;
            int iy = iy2 >> 1; if (iy >= HWD) continue;
            for (int kw = q; kw < 4; kw += 2) {
                int ix2 = ox - kw; if (ix2 < 0) continue;
                int ix = ix2 >> 1; if (ix >= HWD) continue;
                int pix = (b*HWD + iy)*HWD + ix;
                s_pix[cnt] = pix;
                s_kk[cnt]  = kh*4 + kw;
                s_n[cnt]   = g_seln[pix];
                cnt++;
            }
        }
        s_cnt = cnt;
    }
    __syncthreads();
    int cnt = s_cnt;
    if (tid < 128) {
        int s = tid >> 5, t = tid & 31;
        if (s < cnt && t < s_n[s]) {
            s_ch[s][t] = g_selc[s_pix[s]*30 + t];
            s_cf[s][t] = g_self[s_pix[s]*30 + t];
        }
    }
    __syncthreads();

    size_t obase = ((size_t)(b*1156 + oy*34 + ox))*C1P;
    int t2 = tid;
    if (t2 < 150) {
        float ax = 0.f, ay = 0.f;
        const __half2* wtab = (const __half2*)g_wl1h;
        for (int s = 0; s < cnt; s++) {
            int kk = s_kk[s];
            int ns = s_n[s];
            #pragma unroll 4
            for (int t = 0; t < ns; t++) {
                int c = (int)s_ch[s][t];
                float cf = s_cf[s][t];
                float2 wv = __half22float2(wtab[(c*16 + kk)*150 + t2]);
                ax = fmaf(cf, wv.x, ax);
                ay = fmaf(cf, wv.y, ay);
            }
        }
        int co = 2*t2;
        float ox2 = fmaxf(ax + b1[co],   0.f);
        float oy2 = fmaxf(ay + b1[co+1], 0.f);
        ((__half2*)(g_y1h + obase))[t2] = __floats2half2_rn(ox2, oy2);
    } else {
        ((__half2*)(g_y1h + obase))[t2] = __floats2half2_rn(0.f, 0.f);
    }
}

// ---------------- conv2: fp16 HMMA implicit GEMM, M32xN64 warp tiles -------
// M=128 pixels/CTA, N=128 (c2 padded), K = 9 slabs * 320 ch, chunks of 64
// 3-stage cp.async pipeline, one barrier per chunk.
#define STAGE_BYTES 32768
__global__ __launch_bounds__(256, 2) void k_conv2_mma(const float* __restrict__ b2) {
    extern __shared__ char dsm[];
    uint32_t smu = smem_u32(dsm);

    int tid = threadIdx.x;
    int wid = tid >> 5;
    int lane = tid & 31;
    int mg = wid >> 1;        // 0..3 : rows mg*32..+32
    int ng = wid & 1;         // 0..1 : cols ng*64..+64
    int b  = blockIdx.y;
    int p0 = blockIdx.x * 128;

    float acc[2][8][4];
    #pragma unroll
    for (int mt = 0; mt < 2; mt++)
        #pragma unroll
        for (int nt = 0; nt < 8; nt++)
            #pragma unroll
            for (int j = 0; j < 4; j++) acc[mt][nt][j] = 0.f;

    int arow0 = mg*32 +      (lane & 15);
    int arow1 = mg*32 + 16 + (lane & 15);
    int acolb = (lane >> 4) * 16;
    int bn  = (lane & 7) + ((lane >> 4) & 1) * 8;
    int bkb = ((lane >> 3) & 1) * 16;

    auto issue = [&](int i) {
        int s = i % 3;
        int slab = i / 5;
        int c0 = (i - slab*5) * 64;
        int dy = slab / 3, dx = slab - dy*3;
        uint32_t abase = smu + (uint32_t)s * STAGE_BYTES;
        uint32_t bbase = abase + 16384u;
        #pragma unroll
        for (int k = 0; k < 4; k++) {
            int idx = tid + k*256;
            int r = idx >> 3, j = idx & 7;
            int p = p0 + r;
            int oy = p / 36, ox = p - oy*36;
            int iy = oy - dy, ix = ox - dx;
            bool val = (p < 1296) && (iy >= 0) && (iy < 34) && (ix >= 0) && (ix < 34);
            size_t goff = val ? ((size_t)((b*34 + iy)*34 + ix)*C1P + c0 + j*8) : 0;
            cpa16(abase + SWZ128(r*128 + j*16), g_y1h + goff, val ? 16 : 0);
        }
        const __half* wbase = g_w2h + slab*(NTC*C1P) + c0;
        #pragma unroll
        for (int k = 0; k < 4; k++) {
            int idx = tid + k*256;
            int r = idx >> 3, j = idx & 7;
            cpa16(bbase + SWZ128(r*128 + j*16), wbase + r*C1P + j*8, 16);
        }
        cpa_commit();
    };

    auto compute = [&](int s) {
        uint32_t abase = smu + (uint32_t)s * STAGE_BYTES;
        uint32_t bbase = abase + 16384u;
        #pragma unroll
        for (int ks = 0; ks < 4; ks++) {
            uint32_t a0[4], a1[4];
            ldsm4(a0, abase + SWZ128(arow0*128 + ks*32 + acolb));
            ldsm4(a1, abase + SWZ128(arow1*128 + ks*32 + acolb));
            #pragma unroll
            for (int nt = 0; nt < 4; nt++) {
                uint32_t bf[4];
                ldsm4(bf, bbase + SWZ128((ng*64 + nt*16 + bn)*128 + ks*32 + bkb));
                mma16816(acc[0][nt*2],     a0, bf[0], bf[1]);
                mma16816(acc[0][nt*2 + 1], a0, bf[2], bf[3]);
                mma16816(acc[1][nt*2],     a1, bf[0], bf[1]);
                mma16816(acc[1][nt*2 + 1], a1, bf[2], bf[3]);
            }
        }
    };

    issue(0);
    issue(1);
    for (int i = 0; i < 45; i++) {
        if (i <= 42)      asm volatile("cp.async.wait_group 1;" ::: "memory");
        else if (i == 43) asm volatile("cp.async.wait_group 1;" ::: "memory");
        else              asm volatile("cp.async.wait_group 0;" ::: "memory");
        __syncthreads();
        compute(i % 3);
        if (i <= 42) issue(i + 2);
    }

    // epilogue: bias + relu + store f32 NHWC
    int g  = lane >> 2;
    int qp = (lane & 3) * 2;
    #pragma unroll
    for (int mt = 0; mt < 2; mt++) {
        int rbase = p0 + mg*32 + mt*16 + g;
        #pragma unroll
        for (int nt = 0; nt < 8; nt++) {
            int n = ng*64 + nt*8 + qp;
            if (n < 100) {
                float b0v = b2[n], b1v = b2[n + 1];
                if (rbase < 1296) {
                    float2 o;
                    o.x = fmaxf(acc[mt][nt][0] + b0v, 0.f);
                    o.y = fmaxf(acc[mt][nt][1] + b1v, 0.f);
                    *(float2*)&g_y2[((size_t)b*1296 + rbase)*C2 + n] = o;
                }
                if (rbase + 8 < 1296) {
                    float2 o;
                    o.x = fmaxf(acc[mt][nt][2] + b0v, 0.f);
                    o.y = fmaxf(acc[mt][nt][3] + b1v, 0.f);
                    *(float2*)&g_y2[((size_t)b*1296 + rbase + 8)*C2 + n] = o;
                }
            }
        }
    }
}

// ---------------- conv3 (100->3 3x3 transpose) + ReLU + center crop ----------------
__global__ __launch_bounds__(96) void k_conv3(const float* __restrict__ b3,
                                              float* __restrict__ out) {
    __shared__ float s_y2[3*35*50];
    __shared__ float s_w3[9*C2*3];

    int u   = blockIdx.x;
    int b   = blockIdx.y;
    int tid = threadIdx.x;
    int v   = tid % 32;
    int c3  = tid / 32;

    for (int i = tid; i < 9*C2*3; i += 96) s_w3[i] = g_w3m[i];

    float acc = 0.f;
    for (int c0 = 0; c0 < C2; c0 += 50) {
        __syncthreads();
        for (int i = tid; i < 3*35*50; i += 96) {
            int cl = i % 50;
            int t  = i / 50;
            int ix = t % 35;
            int r  = t / 35;
            s_y2[i] = g_y2[((size_t)(b*36 + (u+1+r))*36 + (ix+1))*C2 + c0 + cl];
        }
        __syncthreads();
        for (int dy = 0; dy < 3; dy++) {
            int r = 2 - dy;
            #pragma unroll
            for (int dx = 0; dx < 3; dx++) {
                int col = v + 2 - dx;
                const float* yrow = s_y2 + (r*35 + col)*50;
                const float* wrow = s_w3 + ((dy*3 + dx)*C2 + c0)*3 + c3;
                #pragma unroll 10
                for (int c = 0; c < 50; c++) acc += yrow[c] * wrow[c*3];
            }
        }
    }
    out[((b*3 + c3)*32 + u)*32 + v] = fmaxf(acc + b3[c3], 0.f);
}

// ---------------- launch ----------------
extern "C" void kernel_launch(void* const* d_in, const int* in_sizes, int n_in,
                              void* d_out, int out_size) {
    const float* x    = (const float*)d_in[0];
    const float* phi  = (const float*)d_in[1];
    const float* jump = (const float*)d_in[2];
    const float* w1   = (const float*)d_in[3];
    const float* b1   = (const float*)d_in[4];
    const float* w2   = (const float*)d_in[5];
    const float* b2   = (const float*)d_in[6];
    const float* w3   = (const float*)d_in[7];
    const float* b3   = (const float*)d_in[8];
    float* out = (float*)d_out;

    cudaFuncSetAttribute(k_conv2_mma, cudaFuncAttributeMaxDynamicSharedMemorySize,
                         3*STAGE_BYTES);
    cudaFuncSetAttribute(k_topk, cudaFuncAttributeMaxDynamicSharedMemorySize,
                         TOPK_SMEM);

    k_prep<<<NC + W2H_BLKS + W3M_BLKS, 256>>>(phi, w1, w2, w3);   // 0
    k_topk<<<dim3(8, NB), 256, TOPK_SMEM>>>(x, jump);             // 1
    k_conv1<<<dim3(34*34, NB), 160>>>(b1);                        // 2
    k_conv2_mma<<<dim3(11, NB), 256, 3*STAGE_BYTES>>>(b2);        // 3  <- profiled slot
    k_conv3<<<dim3(32, NB), 96>>>(b3, out);                       // 4
}

// round 12
// speedup vs baseline: 6.3267x; 1.0351x over previous
#include <cuda_runtime.h>
#include <cuda_fp16.h>
#include <cstdint>

#define NB 128
#define NC 500
#define HWD 16
#define HW 256
#define NPIX (NB*HW)          // 32768
#define C1 300
#define C1P 320               // padded channels for fp16 NHWC y1
#define C2 100
#define NTC 128               // padded N for tensor-core conv2 (16 n8-tiles)

// ---------------- device scratch (no allocations allowed) ----------------
__device__ float  g_l1[NC];
__device__ __half g_wl1h[NC*16*C1];       // [c][kk][co] fp16, pre-scaled by l1
__device__ int    g_seln[NPIX];
__device__ short  g_selc[NPIX*30];
__device__ float  g_self[NPIX*30];
__device__ __half g_y1h[(size_t)NB*34*34*C1P];  // NHWC fp16, padded to 320
__device__ __half g_w2h[9*NTC*C1P];             // [slab][c2p][c1p] fp16
__device__ __half g_y2h[(size_t)NB*36*36*C2];   // NHWC fp16
__device__ float  g_w3m[9*C2*3];                // [dy][dx][c1][c3]

// ================= baseline-PTX helpers =================
__device__ __forceinline__ uint32_t smem_u32(const void* p) {
    uint32_t a;
    asm("{ .reg .u64 t; cvta.to.shared.u64 t, %1; cvt.u32.u64 %0, t; }"
        : "=r"(a) : "l"(p));
    return a;
}
#define SWZ128(x) ((x) ^ (((x) >> 3) & 0x70))

__device__ __forceinline__ void cpa16(uint32_t dst, const void* src, int sz) {
    asm volatile("cp.async.cg.shared.global [%0], [%1], 16, %2;"
                 :: "r"(dst), "l"(src), "r"(sz));
}
__device__ __forceinline__ void cpa_commit() {
    asm volatile("cp.async.commit_group;");
}
__device__ __forceinline__ void ldsm4(uint32_t* r, uint32_t addr) {
    asm volatile("ldmatrix.sync.aligned.m8n8.x4.shared.b16 {%0,%1,%2,%3}, [%4];"
        : "=r"(r[0]), "=r"(r[1]), "=r"(r[2]), "=r"(r[3]) : "r"(addr));
}
__device__ __forceinline__ void mma16816(float* c, const uint32_t* a,
                                         uint32_t b0, uint32_t b1) {
    asm volatile("mma.sync.aligned.m16n8k16.row.col.f32.f16.f16.f32 "
        "{%0,%1,%2,%3}, {%4,%5,%6,%7}, {%8,%9}, {%0,%1,%2,%3};"
        : "+f"(c[0]), "+f"(c[1]), "+f"(c[2]), "+f"(c[3])
        : "r"(a[0]), "r"(a[1]), "r"(a[2]), "r"(a[3]), "r"(b0), "r"(b1));
}

// ---------------- consolidated prep: l1 + wl1h + w2h + w3m ----------------
#define W2H_BLKS ((9*NTC*C1P + 255)/256)
#define W3M_BLKS ((9*C2*3 + 255)/256)
__global__ __launch_bounds__(256) void k_prep(const float* __restrict__ phi,
                                              const float* __restrict__ w1,
                                              const float* __restrict__ w2,
                                              const float* __restrict__ w3) {
    int blk = blockIdx.x;
    int tid = threadIdx.x;
    if (blk < NC) {
        __shared__ float red[256];
        int c = blk;
        float s = 0.f;
        for (int d = tid; d < 192; d += 256) s += fabsf(phi[d*NC + c]);
        red[tid] = s;
        __syncthreads();
        for (int off = 128; off; off >>= 1) {
            if (tid < off) red[tid] += red[tid + off];
            __syncthreads();
        }
        float l1 = red[0] + 1e-12f;
        if (tid == 0) g_l1[c] = l1;
        for (int i = tid; i < 16*C1; i += 256) {
            int kk = i / C1, co = i % C1;
            g_wl1h[(c*16 + kk)*C1 + co] = __float2half(l1 * w1[(c*C1 + co)*16 + kk]);
        }
    } else if (blk < NC + W2H_BLKS) {
        int e = (blk - NC)*256 + tid;
        if (e < 9*NTC*C1P) {
            int c1 = e % C1P;
            int t  = e / C1P;
            int c2 = t % NTC;
            int dd = t / NTC;
            int dy = dd / 3, dx = dd % 3;
            float v = (c1 < C1 && c2 < C2) ? w2[((c1*C2 + c2)*3 + dy)*3 + dx] : 0.f;
            g_w2h[e] = __float2half(v);
        }
    } else {
        int e = (blk - NC - W2H_BLKS)*256 + tid;
        if (e < 9*C2*3) {
            int c3 = e % 3;
            int t  = e / 3;
            int c1 = t % C2;
            int dd = t / C2;
            int dy = dd / 3, dx = dd % 3;
            g_w3m[e] = w3[((c1*3 + c3)*3 + dy)*3 + dx];
        }
    }
}

// ---------------- fused transpose + top-30 + saturation ----------------
#define TOPK_SMEM ((NC*33 + NC)*4)
__global__ __launch_bounds__(256) void k_topk(const float* __restrict__ x,
                                              const float* __restrict__ jump_ptr) {
    extern __shared__ float sm[];
    float* sx  = sm;            // [500][33]
    float* sl1 = sm + NC*33;    // [500]

    int b   = blockIdx.y;
    int hw0 = blockIdx.x * 32;
    int tid = threadIdx.x;
    const float* xb = x + ((size_t)b*NC)*HW + hw0;

    for (int i = tid; i < NC*8; i += 256) {
        int c = i >> 3, j = i & 7;
        float4 v = *(const float4*)(xb + c*HW + j*4);
        float* d = sx + c*33 + j*4;
        d[0] = v.x; d[1] = v.y; d[2] = v.z; d[3] = v.w;
    }
    for (int i = tid; i < NC; i += 256) sl1[i] = g_l1[i];
    __syncthreads();

    float jump = *jump_ptr;
    int wid = tid >> 5, lane = tid & 31;

    for (int q = 0; q < 4; q++) {
        int p   = wid*4 + q;
        int pix = b*HW + hw0 + p;

        unsigned u[16];
        #pragma unroll
        for (int t = 0; t < 16; t++) {
            int c = lane + t*32;
            u[t] = (c < NC) ? (__float_as_uint(sx[c*33 + p]) & 0x7fffffffu) : 0u;
        }

        int n = 0;
        for (int it = 0; it < 30; it++) {
            unsigned a0 = max(u[0], u[1]),  a1 = max(u[2], u[3]);
            unsigned a2 = max(u[4], u[5]),  a3 = max(u[6], u[7]);
            unsigned a4 = max(u[8], u[9]),  a5 = max(u[10], u[11]);
            unsigned a6 = max(u[12], u[13]), a7 = max(u[14], u[15]);
            unsigned b0 = max(a0, a1), b1 = max(a2, a3);
            unsigned b2 = max(a4, a5), b3 = max(a6, a7);
            unsigned lm = max(max(b0, b1), max(b2, b3));

            unsigned gm = __reduce_max_sync(0xffffffffu, lm);
            unsigned ball = __ballot_sync(0xffffffffu, lm == gm);
            int leader = __ffs(ball) - 1;
            int c_sel = 0;
            if (lane == leader) {
                int mi = 0;
                #pragma unroll
                for (int t = 15; t >= 0; t--)
                    if (u[t] == gm) { mi = t; u[t] = 0u; }
                c_sel = lane + mi*32;
            }
            c_sel = __shfl_sync(0xffffffffu, c_sel, leader);

            float xv = sx[c_sel*33 + p];
            float th = jump * sl1[c_sel];
            float coef = 0.5f * ((float)((xv > th) - (xv < th)) +
                                 (float)((xv > -th) - (xv < -th)));
            if (coef != 0.f) {
                if (lane == 0) {
                    g_selc[pix*30 + n] = (short)c_sel;
                    g_self[pix*30 + n] = coef;
                }
                n++;
            }
        }
        if (lane == 0) g_seln[pix] = n;
    }
}

// ---------------- conv1 (sparse gather, fp16 table) -> y1h fp16 NHWC/320 ----------------
__global__ __launch_bounds__(160) void k_conv1(const float* __restrict__ b1) {
    __shared__ int   s_cnt;
    __shared__ int   s_pix[4], s_kk[4], s_n[4];
    __shared__ short s_ch[4][32];
    __shared__ float s_cf[4][32];

    int b   = blockIdx.y;
    int oy  = blockIdx.x / 34;
    int ox  = blockIdx.x % 34;
    int tid = threadIdx.x;

    if (tid == 0) {
        int cnt = 0;
        int p = oy & 1, q = ox & 1;
        for (int kh = p; kh < 4; kh += 2) {
            int iy2 = oy - kh; if (iy2 < 0) continue;
            int iy = iy2 >> 1; if (iy >= HWD) continue;
            for (int kw = q; kw < 4; kw += 2) {
                int ix2 = ox - kw; if (ix2 < 0) continue;
                int ix = ix2 >> 1; if (ix >= HWD) continue;
                int pix = (b*HWD + iy)*HWD + ix;
                s_pix[cnt] = pix;
                s_kk[cnt]  = kh*4 + kw;
                s_n[cnt]   = g_seln[pix];
                cnt++;
            }
        }
        s_cnt = cnt;
    }
    __syncthreads();
    int cnt = s_cnt;
    if (tid < 128) {
        int s = tid >> 5, t = tid & 31;
        if (s < cnt && t < s_n[s]) {
            s_ch[s][t] = g_selc[s_pix[s]*30 + t];
            s_cf[s][t] = g_self[s_pix[s]*30 + t];
        }
    }
    __syncthreads();

    size_t obase = ((size_t)(b*1156 + oy*34 + ox))*C1P;
    int t2 = tid;
    if (t2 < 150) {
        float ax = 0.f, ay = 0.f;
        const __half2* wtab = (const __half2*)g_wl1h;
        for (int s = 0; s < cnt; s++) {
            int kk = s_kk[s];
            int ns = s_n[s];
            #pragma unroll 4
            for (int t = 0; t < ns; t++) {
                int c = (int)s_ch[s][t];
                float cf = s_cf[s][t];
                float2 wv = __half22float2(wtab[(c*16 + kk)*150 + t2]);
                ax = fmaf(cf, wv.x, ax);
                ay = fmaf(cf, wv.y, ay);
            }
        }
        int co = 2*t2;
        float ox2 = fmaxf(ax + b1[co],   0.f);
        float oy2 = fmaxf(ay + b1[co+1], 0.f);
        ((__half2*)(g_y1h + obase))[t2] = __floats2half2_rn(ox2, oy2);
    } else {
        ((__half2*)(g_y1h + obase))[t2] = __floats2half2_rn(0.f, 0.f);
    }
}

// ---------------- conv2: fp16 HMMA implicit GEMM, M32xN64 warp tiles -------
// M=128 pixels/CTA, N=128 (c2 padded), K = 9 slabs * 320 ch, chunks of 64
// 3-stage cp.async pipeline, one barrier per chunk, hoisted geometry.
#define STAGE_BYTES 32768
__global__ __launch_bounds__(256, 2) void k_conv2_mma(const float* __restrict__ b2) {
    extern __shared__ char dsm[];
    uint32_t smu = smem_u32(dsm);

    int tid = threadIdx.x;
    int wid = tid >> 5;
    int lane = tid & 31;
    int mg = wid >> 1;        // 0..3 : rows mg*32..+32
    int ng = wid & 1;         // 0..1 : cols ng*64..+64
    int b  = blockIdx.y;
    int p0 = blockIdx.x * 128;

    // ---- hoisted per-thread cp.async geometry (loop-invariant) ----
    int jj = tid & 7;
    int oyk[4], oxk[4], gbase[4];
    uint32_t dstk[4];
    bool pok[4];
    #pragma unroll
    for (int k = 0; k < 4; k++) {
        int r = (tid >> 3) + k*32;
        int p = p0 + r;
        int oy = p / 36, ox = p - oy*36;
        oyk[k] = oy; oxk[k] = ox;
        pok[k] = (p < 1296);
        gbase[k] = ((b*34 + oy)*34 + ox)*C1P + jj*8;
        dstk[k]  = SWZ128(r*128 + jj*16);
    }

    float acc[2][8][4];
    #pragma unroll
    for (int mt = 0; mt < 2; mt++)
        #pragma unroll
        for (int nt = 0; nt < 8; nt++)
            #pragma unroll
            for (int j = 0; j < 4; j++) acc[mt][nt][j] = 0.f;

    int arow0 = mg*32 +      (lane & 15);
    int arow1 = mg*32 + 16 + (lane & 15);
    int acolb = (lane >> 4) * 16;
    int bn  = (lane & 7) + ((lane >> 4) & 1) * 8;
    int bkb = ((lane >> 3) & 1) * 16;

    auto issue = [&](int i) {
        int s = i % 3;
        int slab = i / 5;
        int c0 = (i - slab*5) * 64;
        int dy = slab / 3, dx = slab - dy*3;
        int shift = (dy*34 + dx)*C1P - c0;
        uint32_t abase = smu + (uint32_t)s * STAGE_BYTES;
        uint32_t bbase = abase + 16384u;
        #pragma unroll
        for (int k = 0; k < 4; k++) {
            bool val = pok[k] & (oyk[k] >= dy) & (oyk[k] < 34 + dy)
                              & (oxk[k] >= dx) & (oxk[k] < 34 + dx);
            size_t goff = val ? (size_t)(gbase[k] - shift) : 0;
            cpa16(abase + dstk[k], g_y1h + goff, val ? 16 : 0);
        }
        const __half* wbase = g_w2h + slab*(NTC*C1P) + c0 + jj*8;
        int rr = tid >> 3;
        #pragma unroll
        for (int k = 0; k < 4; k++)
            cpa16(bbase + dstk[k], wbase + (rr + k*32)*C1P, 16);
        cpa_commit();
    };

    auto compute = [&](int s) {
        uint32_t abase = smu + (uint32_t)s * STAGE_BYTES;
        uint32_t bbase = abase + 16384u;
        #pragma unroll
        for (int ks = 0; ks < 4; ks++) {
            uint32_t a0[4], a1[4];
            ldsm4(a0, abase + SWZ128(arow0*128 + ks*32 + acolb));
            ldsm4(a1, abase + SWZ128(arow1*128 + ks*32 + acolb));
            #pragma unroll
            for (int nt = 0; nt < 4; nt++) {
                uint32_t bf[4];
                ldsm4(bf, bbase + SWZ128((ng*64 + nt*16 + bn)*128 + ks*32 + bkb));
                mma16816(acc[0][nt*2],     a0, bf[0], bf[1]);
                mma16816(acc[0][nt*2 + 1], a0, bf[2], bf[3]);
                mma16816(acc[1][nt*2],     a1, bf[0], bf[1]);
                mma16816(acc[1][nt*2 + 1], a1, bf[2], bf[3]);
            }
        }
    };

    issue(0);
    issue(1);
    for (int i = 0; i < 45; i++) {
        if (i <= 43) asm volatile("cp.async.wait_group 1;" ::: "memory");
        else         asm volatile("cp.async.wait_group 0;" ::: "memory");
        __syncthreads();
        compute(i % 3);
        if (i <= 42) issue(i + 2);
    }

    // epilogue: bias + relu + store fp16 NHWC
    int g  = lane >> 2;
    int qp = (lane & 3) * 2;
    #pragma unroll
    for (int mt = 0; mt < 2; mt++) {
        int rbase = p0 + mg*32 + mt*16 + g;
        #pragma unroll
        for (int nt = 0; nt < 8; nt++) {
            int n = ng*64 + nt*8 + qp;
            if (n < 100) {
                float b0v = b2[n], b1v = b2[n + 1];
                if (rbase < 1296) {
                    float o0 = fmaxf(acc[mt][nt][0] + b0v, 0.f);
                    float o1 = fmaxf(acc[mt][nt][1] + b1v, 0.f);
                    *(__half2*)&g_y2h[((size_t)b*1296 + rbase)*C2 + n] =
                        __floats2half2_rn(o0, o1);
                }
                if (rbase + 8 < 1296) {
                    float o0 = fmaxf(acc[mt][nt][2] + b0v, 0.f);
                    float o1 = fmaxf(acc[mt][nt][3] + b1v, 0.f);
                    *(__half2*)&g_y2h[((size_t)b*1296 + rbase + 8)*C2 + n] =
                        __floats2half2_rn(o0, o1);
                }
            }
        }
    }
}

// ---------------- conv3 (100->3 3x3 transpose) + ReLU + center crop -------
// single pass: 3 rows x 35 cols x 100 ch staged as f32 (from fp16 y2),
// weights re-laid [c3][dy][dx][c1] for float4 inner loop.
#define CONV3_SMEM ((3*35*100 + 9*C2*3)*4)
__global__ __launch_bounds__(96) void k_conv3(const float* __restrict__ b3,
                                              float* __restrict__ out) {
    extern __shared__ float cs[];
    float* s_y2 = cs;                 // [3][35][100] f32
    float* s_w3 = cs + 3*35*100;      // [c3][dy][dx][100]

    int u   = blockIdx.x;
    int b   = blockIdx.y;
    int tid = threadIdx.x;
    int v   = tid % 32;
    int c3  = tid / 32;

    // weights: [dy][dx][c1][c3] -> [c3][dy][dx][c1]
    for (int i = tid; i < 9*C2*3; i += 96) {
        int c1 = i % C2;
        int t  = i / C2;
        int dd = t % 9;
        int cc = t / 9;
        s_w3[(cc*9 + dd)*C2 + c1] = g_w3m[(dd*C2 + c1)*3 + cc];
    }
    // y2 rows u+1..u+3, cols 1..35 (fp16 -> f32)
    {
        const __half2* src = (const __half2*)g_y2h;
        for (int i = tid; i < 3*35*50; i += 96) {
            int cl = i % 50;          // half2 index
            int t  = i / 50;
            int ix = t % 35;
            int r  = t / 35;
            float2 vv = __half22float2(
                src[(((size_t)b*1296 + (u+1+r)*36 + (ix+1))*C2 >> 1) + cl]);
            s_y2[(r*35 + ix)*100 + cl*2]     = vv.x;
            s_y2[(r*35 + ix)*100 + cl*2 + 1] = vv.y;
        }
    }
    __syncthreads();

    float acc = 0.f;
    #pragma unroll
    for (int dy = 0; dy < 3; dy++) {
        int r = 2 - dy;
        #pragma unroll
        for (int dx = 0; dx < 3; dx++) {
            int col = v + 2 - dx;
            const float4* yrow = (const float4*)(s_y2 + (r*35 + col)*100);
            const float4* wrow = (const float4*)(s_w3 + (c3*9 + dy*3 + dx)*C2);
            #pragma unroll 5
            for (int c = 0; c < 25; c++) {
                float4 yv = yrow[c];
                float4 wv = wrow[c];
                acc = fmaf(yv.x, wv.x, acc);
                acc = fmaf(yv.y, wv.y, acc);
                acc = fmaf(yv.z, wv.z, acc);
                acc = fmaf(yv.w, wv.w, acc);
            }
        }
    }
    out[((b*3 + c3)*32 + u)*32 + v] = fmaxf(acc + b3[c3], 0.f);
}

// ---------------- launch ----------------
extern "C" void kernel_launch(void* const* d_in, const int* in_sizes, int n_in,
                              void* d_out, int out_size) {
    const float* x    = (const float*)d_in[0];
    const float* phi  = (const float*)d_in[1];
    const float* jump = (const float*)d_in[2];
    const float* w1   = (const float*)d_in[3];
    const float* b1   = (const float*)d_in[4];
    const float* w2   = (const float*)d_in[5];
    const float* b2   = (const float*)d_in[6];
    const float* w3   = (const float*)d_in[7];
    const float* b3   = (const float*)d_in[8];
    float* out = (float*)d_out;

    cudaFuncSetAttribute(k_conv2_mma, cudaFuncAttributeMaxDynamicSharedMemorySize,
                         3*STAGE_BYTES);
    cudaFuncSetAttribute(k_topk, cudaFuncAttributeMaxDynamicSharedMemorySize,
                         TOPK_SMEM);
    cudaFuncSetAttribute(k_conv3, cudaFuncAttributeMaxDynamicSharedMemorySize,
                         CONV3_SMEM);

    k_prep<<<NC + W2H_BLKS + W3M_BLKS, 256>>>(phi, w1, w2, w3);   // 0
    k_topk<<<dim3(8, NB), 256, TOPK_SMEM>>>(x, jump);             // 1
    k_conv1<<<dim3(34*34, NB), 160>>>(b1);                        // 2
    k_conv2_mma<<<dim3(11, NB), 256, 3*STAGE_BYTES>>>(b2);        // 3  <- profiled slot
    k_conv3<<<dim3(32, NB), 96, CONV3_SMEM>>>(b3, out);           // 4
}